// round 8
// baseline (speedup 1.0000x reference)
#include <cuda_runtime.h>
#include <math.h>

#define LOG2E 1.4426950408889634f
typedef unsigned long long ull;

// ---------------- scratch (device globals; no allocation) ----------------
__device__ float g_XI  [128 * 4096];      // in_proj xi, planar [d][hw]
__device__ float g_Zp  [64 * 4096];       // z gate, planar [o][p]
__device__ float g_XCT [4096 * 128];      // conv+silu output, pixel-major [p][d]
__device__ float g_PROJT[4096 * 144];     // x_proj output, pixel-major [p][144]
__device__ float g_YN  [4096 * 1152];     // post-LN window features [p][pos*128+d]
__device__ float g_CORE[4 * 4096 * 64];   // addconv partials (split-k=4) [s][p][o]
__device__ float g_ALc [512 * 16];        // -exp(A_logs) * log2e
__device__ float g_WT  [1152 * 64];       // addconv_w transposed [pos*128+d][o]
__device__ float g_WoT [64 * 64];         // out_proj_w^T [c][o]
__device__ float g_WsT [64 * 64];         // skip_w^T [c][o]
__device__ int   g_fastA = 1;             // A has geometric structure (sticky)

// ---------------- helpers ----------------
__device__ __forceinline__ float ex2f_fast(float x) {
    float y; asm("ex2.approx.f32 %0, %1;" : "=f"(y) : "f"(x)); return y;
}
__device__ __forceinline__ float softplusf(float x) {
    return x > 15.f ? x : __logf(1.f + __expf(x));
}
__device__ __forceinline__ float siluf(float x) {
    return x / (1.f + __expf(-x));
}
__device__ __forceinline__ int refl(int v) {
    return v < 0 ? -v : (v > 63 ? 126 - v : v);
}
__device__ __forceinline__ ull pack2(float a, float b) {
    ull r; asm("mov.b64 %0, {%1,%2};" : "=l"(r) : "f"(a), "f"(b)); return r;
}
__device__ __forceinline__ void unpack2(ull v, float& a, float& b) {
    asm("mov.b64 {%0,%1}, %2;" : "=f"(a), "=f"(b) : "l"(v));
}
__device__ __forceinline__ ull fma2(ull a, ull b, ull c) {
    ull d; asm("fma.rn.f32x2 %0, %1, %2, %3;" : "=l"(d) : "l"(a), "l"(b), "l"(c)); return d;
}
__device__ __forceinline__ ull mul2(ull a, ull b) {
    ull d; asm("mul.rn.f32x2 %0, %1, %2;" : "=l"(d) : "l"(a), "l"(b)); return d;
}

// ---------------- K0: precompute ----------------
__global__ void k_pre(const float* __restrict__ A_logs,
                      const float* __restrict__ addconv_w,
                      const float* __restrict__ out_proj_w,
                      const float* __restrict__ skip_w) {
    int idx = blockIdx.x * 256 + threadIdx.x;
    if (idx < 73728) {
        int o = idx & 63; int rest = idx >> 6;
        int d = rest & 127; int pos = rest >> 7;
        g_WT[idx] = addconv_w[o * 1152 + d * 9 + pos];
    } else if (idx < 73728 + 8192) {
        int j = idx - 73728;
        float e = expf(A_logs[j]);
        g_ALc[j] = -e * LOG2E;
        int n = j & 15;
        float e0 = expf(A_logs[j & ~15]);
        if (fabsf(e - (float)(n + 1) * e0) > 1e-4f * fmaxf(e, 1e-6f))
            atomicAnd(&g_fastA, 0);
    } else if (idx < 73728 + 8192 + 4096) {
        int j = idx - 73728 - 8192;
        int o = j & 63, c = j >> 6;
        g_WoT[j] = out_proj_w[o * 64 + c];
    } else if (idx < 73728 + 8192 + 8192) {
        int j = idx - 73728 - 8192 - 4096;
        int o = j & 63, c = j >> 6;
        g_WsT[j] = skip_w[o * 64 + c];
    }
}

// ---------------- K1: fused LN + in_proj GEMM; grid (128, 6) ----------------
__global__ void __launch_bounds__(256) k_inproj(
    const float* __restrict__ x, const float* __restrict__ g,
    const float* __restrict__ b, const float* __restrict__ ipw) {
    __shared__ float xs[32][65];
    __shared__ float ws[64][34];
    const int tid = threadIdx.x;
    const int warp = tid >> 5, lane = tid & 31;
    const int p0 = blockIdx.x * 32;
    const int cg = blockIdx.y * 32;

    #pragma unroll
    for (int i = 0; i < 4; i++) {
        int px = warp * 4 + i;
        int p = p0 + px;
        float x0 = x[p * 64 + lane], x1 = x[p * 64 + lane + 32];
        float s = x0 + x1;
        #pragma unroll
        for (int off = 16; off > 0; off >>= 1) s += __shfl_xor_sync(0xffffffffu, s, off);
        float mu = s * (1.f / 64.f);
        float d0 = x0 - mu, d1 = x1 - mu;
        float q = d0 * d0 + d1 * d1;
        #pragma unroll
        for (int off = 16; off > 0; off >>= 1) q += __shfl_xor_sync(0xffffffffu, q, off);
        float rstd = rsqrtf(q * (1.f / 64.f) + 1e-5f);
        xs[px][lane]      = d0 * rstd * g[lane]      + b[lane];
        xs[px][lane + 32] = d1 * rstd * g[lane + 32] + b[lane + 32];
    }
    for (int e = tid; e < 2048; e += 256) {
        int cc = e >> 6, k = e & 63;
        ws[k][cc] = ipw[(cg + cc) * 64 + k];
    }
    __syncthreads();
    ull a0 = 0ull, a1 = 0ull;
    #pragma unroll
    for (int k = 0; k < 64; k++) {
        float xv = xs[lane][k];
        ull xp = pack2(xv, xv);
        a0 = fma2(xp, *(const ull*)&ws[k][4 * warp],     a0);
        a1 = fma2(xp, *(const ull*)&ws[k][4 * warp + 2], a1);
    }
    int p = p0 + lane;
    float r0, r1, r2, r3;
    unpack2(a0, r0, r1); unpack2(a1, r2, r3);
    int c = cg + 4 * warp;
    float rv[4] = {r0, r1, r2, r3};
    #pragma unroll
    for (int j = 0; j < 4; j++) {
        int cj = c + j;
        if (cj < 128) g_XI[cj * 4096 + p] = rv[j];
        else          g_Zp[(cj - 128) * 4096 + p] = rv[j];
    }
}

// ---------------- K2: depthwise 3x3 conv, smem row staging ----------------
__global__ void __launch_bounds__(256) k_conv(
    const float* __restrict__ cw, const float* __restrict__ cb) {
    __shared__ float srow[3][16][64];
    __shared__ float cwsm[16][9];
    __shared__ float cbsm[16];
    const int h  = blockIdx.x >> 3, dg = blockIdx.x & 7;
    const int tid = threadIdx.x;

    for (int e = tid; e < 3072; e += 256) {
        int r = e >> 10, dl = (e >> 6) & 15, ww = e & 63;
        int hh = h + r - 1;
        srow[r][dl][ww] = (hh < 0 || hh > 63) ? 0.f
            : g_XI[(dg * 16 + dl) * 4096 + hh * 64 + ww];
    }
    if (tid < 144) cwsm[tid / 9][tid % 9] = cw[(dg * 16 + tid / 9) * 9 + tid % 9];
    if (tid < 16)  cbsm[tid] = cb[dg * 16 + tid];
    __syncthreads();

    const int w = tid & 63, q = tid >> 6;
    float o[4];
    #pragma unroll
    for (int i = 0; i < 4; i++) {
        int dl = q * 4 + i;
        float acc = cbsm[dl];
        #pragma unroll
        for (int ki = 0; ki < 3; ki++) {
            if (w > 0)  acc = fmaf(cwsm[dl][ki * 3 + 0], srow[ki][dl][w - 1], acc);
                        acc = fmaf(cwsm[dl][ki * 3 + 1], srow[ki][dl][w],     acc);
            if (w < 63) acc = fmaf(cwsm[dl][ki * 3 + 2], srow[ki][dl][w + 1], acc);
        }
        o[i] = siluf(acc);
    }
    *(float4*)(g_XCT + (h * 64 + w) * 128 + dg * 16 + q * 4) =
        make_float4(o[0], o[1], o[2], o[3]);
}

// ---------------- K3: x_proj GEMM v4: 8px x 2c per thread, LDS.128 ----------------
// block: 128 px x 36 c; 288 threads = 16 pxg x 18 cq; grid (32, 4)
__global__ void __launch_bounds__(288) k_xproj(const float* __restrict__ xpw) {
    __shared__ __align__(16) float xcT[32][132];   // [k-local][px]
    __shared__ ull wsd[32][36];                    // duplicated weight pairs [k][c]
    const int tid = threadIdx.x;
    const int pxg = tid & 15;
    const int cq  = tid >> 4;
    const int p0 = blockIdx.x * 128;
    const int cg = blockIdx.y * 36;

    ull a0 = 0ull, a1 = 0ull, a2 = 0ull, a3 = 0ull;
    ull b0 = 0ull, b1 = 0ull, b2 = 0ull, b3 = 0ull;

    for (int kb = 0; kb < 128; kb += 32) {
        __syncthreads();
        for (int e = tid; e < 4096; e += 288) {
            int k = e & 31, px = e >> 5;
            xcT[k][px] = g_XCT[(p0 + px) * 128 + kb + k];
        }
        for (int e = tid; e < 1152; e += 288) {
            int k = e & 31, c = e >> 5;
            float wv = xpw[(cg + c) * 128 + kb + k];
            wsd[k][c] = pack2(wv, wv);
        }
        __syncthreads();
        #pragma unroll
        for (int k = 0; k < 32; k++) {
            const float* xrow = &xcT[k][pxg * 8];
            ull xp0 = *(const ull*)(xrow);
            ull xp1 = *(const ull*)(xrow + 2);
            ull xp2 = *(const ull*)(xrow + 4);
            ull xp3 = *(const ull*)(xrow + 6);
            ull w0 = wsd[k][cq * 2];
            ull w1 = wsd[k][cq * 2 + 1];
            a0 = fma2(xp0, w0, a0); a1 = fma2(xp1, w0, a1);
            a2 = fma2(xp2, w0, a2); a3 = fma2(xp3, w0, a3);
            b0 = fma2(xp0, w1, b0); b1 = fma2(xp1, w1, b1);
            b2 = fma2(xp2, w1, b2); b3 = fma2(xp3, w1, b3);
        }
    }
    float v[8];
    int c = cg + cq * 2;
    unpack2(a0, v[0], v[1]); unpack2(a1, v[2], v[3]);
    unpack2(a2, v[4], v[5]); unpack2(a3, v[6], v[7]);
    #pragma unroll
    for (int i = 0; i < 8; i++)
        g_PROJT[(p0 + pxg * 8 + i) * 144 + c] = v[i];
    unpack2(b0, v[0], v[1]); unpack2(b1, v[2], v[3]);
    unpack2(b2, v[4], v[5]); unpack2(b3, v[6], v[7]);
    #pragma unroll
    for (int i = 0; i < 8; i++)
        g_PROJT[(p0 + pxg * 8 + i) * 144 + c + 1] = v[i];
}

// ---------------- K4: selective scan + combine + per-position LN ----------------
__global__ void __launch_bounds__(256) k_scan(
    const float* __restrict__ dtw, const float* __restrict__ dtb,
    const float* __restrict__ Dsp, const float* __restrict__ ong,
    const float* __restrict__ onb) {
    const int half = threadIdx.x >> 7;
    const int tid  = threadIdx.x & 127;
    const int p = blockIdx.x * 2 + half;
    const int h = p >> 6, w = p & 63;
    const int d = tid;
    __shared__ __align__(16) float win[2][9][144];
    __shared__ float redS[2][9][4], redQ[2][9][4];
    __shared__ float mu_s[2][9], rs_s[2][9];

    const int fastA = g_fastA;

    for (int e = tid; e < 9 * 36; e += 128) {
        int pos = e / 36, c4 = e - pos * 36;
        int i = pos / 3, j = pos - 3 * (pos / 3);
        int hh = refl(h - 1 + i), ww = refl(w - 1 + j);
        ((float4*)win[half][pos])[c4] =
            ((const float4*)(g_PROJT + (hh * 64 + ww) * 144))[c4];
    }
    float u9[9];
    #pragma unroll
    for (int pos = 0; pos < 9; pos++) {
        int i = pos / 3, j = pos % 3;
        int hh = refl(h - 1 + i), ww = refl(w - 1 + j);
        u9[pos] = g_XCT[(hh * 64 + ww) * 128 + d];
    }
    __syncthreads();

    constexpr int POS[4][9] = {
        {0,1,2,3,4,5,6,7,8},
        {0,3,6,1,4,7,2,5,8},
        {8,7,6,5,4,3,2,1,0},
        {8,5,2,7,4,1,6,3,0}};
    constexpr int PKB[4] = {0, 72, 36, 108};

    float yw[9];
    #pragma unroll
    for (int t = 0; t < 9; t++) yw[t] = 0.f;

    #pragma unroll
    for (int k = 0; k < 4; k++) {
        int kd = k * 128 + d;
        float4 dw = __ldg((const float4*)(dtw + kd * 4));
        float db = __ldg(dtb + kd);
        float Dv = __ldg(Dsp + kd);
        float AL0 = g_ALc[kd * 16];
        float delta[9];
        #pragma unroll
        for (int l = 0; l < 9; l++) {
            float4 xr = *(const float4*)&win[half][POS[k][l]][PKB[k]];
            float s = db;
            s = fmaf(dw.x, xr.x, s); s = fmaf(dw.y, xr.y, s);
            s = fmaf(dw.z, xr.z, s); s = fmaf(dw.w, xr.w, s);
            delta[l] = softplusf(s);
        }
        ull hp[8];
        #pragma unroll
        for (int j = 0; j < 8; j++) hp[j] = 0ull;
        #pragma unroll
        for (int l = 0; l < 9; l++) {
            const int pos = POS[k][l];
            float dl = delta[l];
            float du = dl * u9[pos];
            ull dup = pack2(du, du);
            const ull* Bp = (const ull*)&win[half][pos][PKB[k] + 4];
            const ull* Cp = (const ull*)&win[half][pos][PKB[k] + 20];
            ull yp = 0ull;
            if (fastA) {
                float r  = ex2f_fast(dl * AL0);
                float r2 = r * r;
                ull rr  = pack2(r2, r2);
                ull dAp = pack2(r, r2);
                #pragma unroll
                for (int j = 0; j < 8; j++) {
                    if (j) dAp = mul2(dAp, rr);
                    hp[j] = fma2(hp[j], dAp, mul2(dup, Bp[j]));
                    yp = fma2(hp[j], Cp[j], yp);
                }
            } else {
                #pragma unroll
                for (int j = 0; j < 8; j++) {
                    float2 al = *(const float2*)(g_ALc + kd * 16 + 2 * j);
                    ull dAp = pack2(ex2f_fast(dl * al.x), ex2f_fast(dl * al.y));
                    hp[j] = fma2(hp[j], dAp, mul2(dup, Bp[j]));
                    yp = fma2(hp[j], Cp[j], yp);
                }
            }
            float ylo, yhi; unpack2(yp, ylo, yhi);
            yw[pos] += fmaf(Dv, u9[pos], ylo + yhi);
        }
    }

    int warp = tid >> 5, lane = tid & 31;
    #pragma unroll
    for (int pos = 0; pos < 9; pos++) {
        float v = yw[pos], q = v * v;
        #pragma unroll
        for (int off = 16; off > 0; off >>= 1) {
            v += __shfl_xor_sync(0xffffffffu, v, off);
            q += __shfl_xor_sync(0xffffffffu, q, off);
        }
        if (lane == 0) { redS[half][pos][warp] = v; redQ[half][pos][warp] = q; }
    }
    __syncthreads();
    if (tid < 9) {
        float s = redS[half][tid][0] + redS[half][tid][1] + redS[half][tid][2] + redS[half][tid][3];
        float q = redQ[half][tid][0] + redQ[half][tid][1] + redQ[half][tid][2] + redQ[half][tid][3];
        float mu = s * (1.f / 128.f);
        float var = q * (1.f / 128.f) - mu * mu;
        mu_s[half][tid] = mu;
        rs_s[half][tid] = rsqrtf(var + 1e-5f);
    }
    __syncthreads();
    float gg = ong[d], bb = onb[d];
    #pragma unroll
    for (int pos = 0; pos < 9; pos++)
        g_YN[p * 1152 + pos * 128 + d] =
            (yw[pos] - mu_s[half][pos]) * rs_s[half][pos] * gg + bb;
}

// ---------------- K5: addconv GEMM v2: 8px x 2c, LDS.128; grid (32, 4) ----------------
__global__ void __launch_bounds__(512) k_addconv() {
    __shared__ __align__(16) float ynT[32][132];
    __shared__ ull wsd[32][64];
    const int tid = threadIdx.x;
    const int pxg = tid & 15;
    const int cq  = tid >> 4;
    const int p0 = blockIdx.x * 128;
    const int split = blockIdx.y;
    const int kb0 = split * 288;

    ull a0 = 0ull, a1 = 0ull, a2 = 0ull, a3 = 0ull;
    ull b0 = 0ull, b1 = 0ull, b2 = 0ull, b3 = 0ull;

    for (int kt = 0; kt < 288; kt += 32) {
        __syncthreads();
        for (int e = tid; e < 4096; e += 512) {
            int k = e & 31, px = e >> 5;
            ynT[k][px] = g_YN[(p0 + px) * 1152 + kb0 + kt + k];
        }
        for (int e = tid; e < 2048; e += 512) {
            int k = e & 31, c = e >> 5;
            float wv = g_WT[(kb0 + kt + k) * 64 + c];
            wsd[k][c] = pack2(wv, wv);
        }
        __syncthreads();
        #pragma unroll
        for (int k = 0; k < 32; k++) {
            const float* xrow = &ynT[k][pxg * 8];
            ull xp0 = *(const ull*)(xrow);
            ull xp1 = *(const ull*)(xrow + 2);
            ull xp2 = *(const ull*)(xrow + 4);
            ull xp3 = *(const ull*)(xrow + 6);
            ull w0 = wsd[k][cq * 2];
            ull w1 = wsd[k][cq * 2 + 1];
            a0 = fma2(xp0, w0, a0); a1 = fma2(xp1, w0, a1);
            a2 = fma2(xp2, w0, a2); a3 = fma2(xp3, w0, a3);
            b0 = fma2(xp0, w1, b0); b1 = fma2(xp1, w1, b1);
            b2 = fma2(xp2, w1, b2); b3 = fma2(xp3, w1, b3);
        }
    }
    float v[8];
    int c = cq * 2;
    float* base = g_CORE + split * 262144;
    unpack2(a0, v[0], v[1]); unpack2(a1, v[2], v[3]);
    unpack2(a2, v[4], v[5]); unpack2(a3, v[6], v[7]);
    #pragma unroll
    for (int i = 0; i < 8; i++)
        base[(p0 + pxg * 8 + i) * 64 + c] = v[i];
    unpack2(b0, v[0], v[1]); unpack2(b1, v[2], v[3]);
    unpack2(b2, v[4], v[5]); unpack2(b3, v[6], v[7]);
    #pragma unroll
    for (int i = 0; i < 8; i++)
        base[(p0 + pxg * 8 + i) * 64 + c + 1] = v[i];
}

// ---------------- K6: gate + out_proj + skip (16 px/block) ----------------
__global__ void __launch_bounds__(256) k_epilogue(
    const float* __restrict__ x, const float* __restrict__ acb,
    const float* __restrict__ skip_b, float* __restrict__ out) {
    __shared__ float ov[16][65], xv[16][65], zsm[16][65];
    __shared__ float wo[64][65], ws[64][65];
    const int tid = threadIdx.x;
    const int o = tid & 63, pg = tid >> 6;
    const int p0 = blockIdx.x * 16;

    for (int e = tid; e < 4096; e += 256) {
        int c = e >> 6, oo = e & 63;
        wo[c][oo] = g_WoT[e];
        ws[c][oo] = g_WsT[e];
    }
    #pragma unroll
    for (int i = 0; i < 4; i++) {
        int idx = tid + i * 256;
        int px2 = idx & 15, o2 = idx >> 4;
        zsm[px2][o2] = g_Zp[o2 * 4096 + p0 + px2];
    }
    __syncthreads();
    float acbv = __ldg(acb + o);
    #pragma unroll
    for (int i = 0; i < 4; i++) {
        int px = pg * 4 + i;
        int p = p0 + px;
        float core = g_CORE[p * 64 + o] + g_CORE[262144 + p * 64 + o]
                   + g_CORE[524288 + p * 64 + o] + g_CORE[786432 + p * 64 + o] + acbv;
        ov[px][o] = core * siluf(zsm[px][o]);
        xv[px][o] = x[p * 64 + o];
    }
    __syncthreads();
    float acc[4];
    float sb = __ldg(skip_b + o);
    #pragma unroll
    for (int i = 0; i < 4; i++) acc[i] = sb;
    #pragma unroll 4
    for (int c = 0; c < 64; c++) {
        float wov = wo[c][o], wsv = ws[c][o];
        #pragma unroll
        for (int i = 0; i < 4; i++) {
            int px = pg * 4 + i;
            acc[i] = fmaf(ov[px][c], wov, acc[i]);
            acc[i] = fmaf(xv[px][c], wsv, acc[i]);
        }
    }
    #pragma unroll
    for (int i = 0; i < 4; i++)
        out[(p0 + pg * 4 + i) * 64 + o] = acc[i];
}

// ---------------- launch ----------------
extern "C" void kernel_launch(void* const* d_in, const int* in_sizes, int n_in,
                              void* d_out, int out_size) {
    const float* x          = (const float*)d_in[0];
    const float* in_norm_g  = (const float*)d_in[1];
    const float* in_norm_b  = (const float*)d_in[2];
    const float* in_proj_w  = (const float*)d_in[3];
    const float* conv_w     = (const float*)d_in[4];
    const float* conv_b     = (const float*)d_in[5];
    const float* x_proj_w   = (const float*)d_in[6];
    const float* dt_w       = (const float*)d_in[7];
    const float* dt_b       = (const float*)d_in[8];
    const float* A_logs     = (const float*)d_in[9];
    const float* Ds         = (const float*)d_in[10];
    const float* out_norm_g = (const float*)d_in[11];
    const float* out_norm_b = (const float*)d_in[12];
    const float* addconv_w  = (const float*)d_in[13];
    const float* addconv_b  = (const float*)d_in[14];
    const float* skip_w     = (const float*)d_in[15];
    const float* skip_b     = (const float*)d_in[16];
    const float* out_proj_w = (const float*)d_in[17];
    float* out = (float*)d_out;

    k_pre<<<352, 256>>>(A_logs, addconv_w, out_proj_w, skip_w);
    k_inproj<<<dim3(128, 6), 256>>>(x, in_norm_g, in_norm_b, in_proj_w);
    k_conv<<<512, 256>>>(conv_w, conv_b);
    k_xproj<<<dim3(32, 4), 288>>>(x_proj_w);
    k_scan<<<2048, 256>>>(dt_w, dt_b, Ds, out_norm_g, out_norm_b);
    k_addconv<<<dim3(32, 4), 512>>>();
    k_epilogue<<<256, 256>>>(x, addconv_b, skip_b, out);
}

// round 9
// speedup vs baseline: 1.0543x; 1.0543x over previous
#include <cuda_runtime.h>
#include <math.h>

#define LOG2E 1.4426950408889634f
typedef unsigned long long ull;

// ---------------- scratch (device globals; no allocation) ----------------
__device__ float g_XN  [4096 * 64];       // layernormed input [p][c]
__device__ float g_XI  [128 * 4096];      // in_proj xi, planar [d][hw]
__device__ float g_Zp  [64 * 4096];       // z gate, planar [o][p]
__device__ float g_XCT [4096 * 128];      // conv+silu output, pixel-major [p][d]
__device__ float g_PROJT[4096 * 144];     // x_proj output, pixel-major [p][144]
__device__ float g_YN  [4096 * 1152];     // post-LN window features [p][pos*128+d]
__device__ float g_CORE[4 * 4096 * 64];   // addconv partials (split-k=4) [s][p][o]
__device__ float g_ALc [512 * 16];        // -exp(A_logs) * log2e
__device__ float g_WT  [1152 * 64];       // addconv_w transposed [pos*128+d][o]
__device__ float g_WoT [64 * 64];         // out_proj_w^T [c][o]
__device__ float g_WsT [64 * 64];         // skip_w^T [c][o]
__device__ int   g_fastA = 1;             // A has geometric structure (sticky)

// ---------------- helpers ----------------
__device__ __forceinline__ float ex2f_fast(float x) {
    float y; asm("ex2.approx.f32 %0, %1;" : "=f"(y) : "f"(x)); return y;
}
__device__ __forceinline__ float softplusf(float x) {
    return x > 15.f ? x : __logf(1.f + __expf(x));
}
__device__ __forceinline__ float siluf(float x) {
    return x / (1.f + __expf(-x));
}
__device__ __forceinline__ int refl(int v) {
    return v < 0 ? -v : (v > 63 ? 126 - v : v);
}
__device__ __forceinline__ ull pack2(float a, float b) {
    ull r; asm("mov.b64 %0, {%1,%2};" : "=l"(r) : "f"(a), "f"(b)); return r;
}
__device__ __forceinline__ void unpack2(ull v, float& a, float& b) {
    asm("mov.b64 {%0,%1}, %2;" : "=f"(a), "=f"(b) : "l"(v));
}
__device__ __forceinline__ ull fma2(ull a, ull b, ull c) {
    ull d; asm("fma.rn.f32x2 %0, %1, %2, %3;" : "=l"(d) : "l"(a), "l"(b), "l"(c)); return d;
}
__device__ __forceinline__ ull mul2(ull a, ull b) {
    ull d; asm("mul.rn.f32x2 %0, %1, %2;" : "=l"(d) : "l"(a), "l"(b)); return d;
}

// ---------------- K0: precompute ----------------
__global__ void k_pre(const float* __restrict__ A_logs,
                      const float* __restrict__ addconv_w,
                      const float* __restrict__ out_proj_w,
                      const float* __restrict__ skip_w) {
    int idx = blockIdx.x * 256 + threadIdx.x;
    if (idx < 73728) {
        int o = idx & 63; int rest = idx >> 6;
        int d = rest & 127; int pos = rest >> 7;
        g_WT[idx] = addconv_w[o * 1152 + d * 9 + pos];
    } else if (idx < 73728 + 8192) {
        int j = idx - 73728;
        float e = expf(A_logs[j]);
        g_ALc[j] = -e * LOG2E;
        int n = j & 15;
        float e0 = expf(A_logs[j & ~15]);
        if (fabsf(e - (float)(n + 1) * e0) > 1e-4f * fmaxf(e, 1e-6f))
            atomicAnd(&g_fastA, 0);
    } else if (idx < 73728 + 8192 + 4096) {
        int j = idx - 73728 - 8192;
        int o = j & 63, c = j >> 6;
        g_WoT[j] = out_proj_w[o * 64 + c];
    } else if (idx < 73728 + 8192 + 8192) {
        int j = idx - 73728 - 8192 - 4096;
        int o = j & 63, c = j >> 6;
        g_WsT[j] = skip_w[o * 64 + c];
    }
}

// ---------------- K1a: layernorm ----------------
__global__ void __launch_bounds__(256) k_ln(
    const float* __restrict__ x, const float* __restrict__ g,
    const float* __restrict__ b) {
    int warp = threadIdx.x >> 5, lane = threadIdx.x & 31;
    int p = blockIdx.x * 8 + warp;
    float x0 = x[p * 64 + lane], x1 = x[p * 64 + lane + 32];
    float s = x0 + x1;
    #pragma unroll
    for (int off = 16; off > 0; off >>= 1) s += __shfl_xor_sync(0xffffffffu, s, off);
    float mu = s * (1.f / 64.f);
    float d0 = x0 - mu, d1 = x1 - mu;
    float q = d0 * d0 + d1 * d1;
    #pragma unroll
    for (int off = 16; off > 0; off >>= 1) q += __shfl_xor_sync(0xffffffffu, q, off);
    float rstd = rsqrtf(q * (1.f / 64.f) + 1e-5f);
    g_XN[p * 64 + lane]      = d0 * rstd * g[lane]      + b[lane];
    g_XN[p * 64 + lane + 32] = d1 * rstd * g[lane + 32] + b[lane + 32];
}

// ---------------- K1b: in_proj GEMM; grid (128, 6) ----------------
__global__ void __launch_bounds__(256) k_inproj(const float* __restrict__ ipw) {
    __shared__ float xs[32][65];
    __shared__ float ws[64][34];
    const int tid = threadIdx.x;
    const int warp = tid >> 5, lane = tid & 31;
    const int p0 = blockIdx.x * 32;
    const int cg = blockIdx.y * 32;
    for (int e = tid; e < 2048; e += 256) {
        int px = e >> 6, k = e & 63;
        xs[px][k] = g_XN[(p0 + px) * 64 + k];
    }
    for (int e = tid; e < 2048; e += 256) {
        int cc = e >> 6, k = e & 63;
        ws[k][cc] = ipw[(cg + cc) * 64 + k];
    }
    __syncthreads();
    ull a0 = 0ull, a1 = 0ull;
    #pragma unroll
    for (int k = 0; k < 64; k++) {
        float xv = xs[lane][k];
        ull xp = pack2(xv, xv);
        a0 = fma2(xp, *(const ull*)&ws[k][4 * warp],     a0);
        a1 = fma2(xp, *(const ull*)&ws[k][4 * warp + 2], a1);
    }
    int p = p0 + lane;
    float r0, r1, r2, r3;
    unpack2(a0, r0, r1); unpack2(a1, r2, r3);
    int c = cg + 4 * warp;
    float rv[4] = {r0, r1, r2, r3};
    #pragma unroll
    for (int j = 0; j < 4; j++) {
        int cj = c + j;
        if (cj < 128) g_XI[cj * 4096 + p] = rv[j];
        else          g_Zp[(cj - 128) * 4096 + p] = rv[j];
    }
}

// ---------------- K2: depthwise 3x3 conv (zero pad) + bias + silu ----------------
__global__ void __launch_bounds__(256) k_conv(
    const float* __restrict__ cw, const float* __restrict__ cb) {
    const int h  = blockIdx.x >> 3, dg = blockIdx.x & 7;
    const int tid = threadIdx.x;
    const int w = tid & 63, q = tid >> 6;
    const int d0 = dg * 16 + q * 4;
    float o[4];
    #pragma unroll
    for (int i = 0; i < 4; i++) {
        int d = d0 + i;
        float acc = __ldg(cb + d);
        #pragma unroll
        for (int ki = 0; ki < 3; ki++) {
            int hh = h + ki - 1;
            if (hh < 0 || hh > 63) continue;
            const float* row = g_XI + d * 4096 + hh * 64 + w;
            if (w > 0)  acc = fmaf(__ldg(cw + d * 9 + ki * 3 + 0), row[-1], acc);
                        acc = fmaf(__ldg(cw + d * 9 + ki * 3 + 1), row[0],  acc);
            if (w < 63) acc = fmaf(__ldg(cw + d * 9 + ki * 3 + 2), row[1],  acc);
        }
        o[i] = siluf(acc);
    }
    *(float4*)(g_XCT + (h * 64 + w) * 128 + d0) = make_float4(o[0], o[1], o[2], o[3]);
}

// ---------------- K3: x_proj GEMM v5: 4px x 4c per thread; grid (64, 4), 144 thr ----------------
// block: 64 px x 36 c = 16 pxg x 9 cg4
__global__ void __launch_bounds__(144) k_xproj(const float* __restrict__ xpw) {
    __shared__ __align__(16) float xcT[32][68];   // [k-local][px]
    __shared__ __align__(16) ull wsd[32][36];     // dup weight pairs [k][c]
    const int tid = threadIdx.x;
    const int pxg = tid % 16;
    const int cg4 = tid / 16;          // 0..8
    const int p0 = blockIdx.x * 64;
    const int cg = blockIdx.y * 36;

    ull acc[2][4];
    #pragma unroll
    for (int i = 0; i < 2; i++)
        #pragma unroll
        for (int j = 0; j < 4; j++) acc[i][j] = 0ull;

    for (int kb = 0; kb < 128; kb += 32) {
        __syncthreads();
        for (int e = tid; e < 2048; e += 144) {
            int k = e & 31, px = e >> 5;
            xcT[k][px] = g_XCT[(p0 + px) * 128 + kb + k];
        }
        for (int e = tid; e < 1152; e += 144) {
            int k = e & 31, c = e >> 5;
            float wv = xpw[(cg + c) * 128 + kb + k];
            wsd[k][c] = pack2(wv, wv);
        }
        __syncthreads();
        #pragma unroll
        for (int k = 0; k < 32; k++) {
            longlong2 xq = *(const longlong2*)&xcT[k][pxg * 4];
            ull xp0 = (ull)xq.x, xp1 = (ull)xq.y;
            longlong2 wq0 = *(const longlong2*)&wsd[k][cg4 * 4];
            longlong2 wq1 = *(const longlong2*)&wsd[k][cg4 * 4 + 2];
            ull w0 = (ull)wq0.x, w1 = (ull)wq0.y, w2 = (ull)wq1.x, w3 = (ull)wq1.y;
            acc[0][0] = fma2(xp0, w0, acc[0][0]); acc[1][0] = fma2(xp1, w0, acc[1][0]);
            acc[0][1] = fma2(xp0, w1, acc[0][1]); acc[1][1] = fma2(xp1, w1, acc[1][1]);
            acc[0][2] = fma2(xp0, w2, acc[0][2]); acc[1][2] = fma2(xp1, w2, acc[1][2]);
            acc[0][3] = fma2(xp0, w3, acc[0][3]); acc[1][3] = fma2(xp1, w3, acc[1][3]);
        }
    }
    const int c0 = cg + cg4 * 4;
    #pragma unroll
    for (int j = 0; j < 4; j++) {
        float v0, v1, v2, v3;
        unpack2(acc[0][j], v0, v1);
        unpack2(acc[1][j], v2, v3);
        g_PROJT[(p0 + pxg * 4 + 0) * 144 + c0 + j] = v0;
        g_PROJT[(p0 + pxg * 4 + 1) * 144 + c0 + j] = v1;
        g_PROJT[(p0 + pxg * 4 + 2) * 144 + c0 + j] = v2;
        g_PROJT[(p0 + pxg * 4 + 3) * 144 + c0 + j] = v3;
    }
}

// ---------------- K4: selective scan + combine + per-position LN (R4 proven) ----------------
__global__ void __launch_bounds__(256) k_scan(
    const float* __restrict__ dtw, const float* __restrict__ dtb,
    const float* __restrict__ Dsp, const float* __restrict__ ong,
    const float* __restrict__ onb) {
    const int half = threadIdx.x >> 7;
    const int tid  = threadIdx.x & 127;
    const int p = blockIdx.x * 2 + half;
    const int h = p >> 6, w = p & 63;
    const int d = tid;
    __shared__ __align__(16) float win[2][9][144];
    __shared__ float redS[2][9][4], redQ[2][9][4];
    __shared__ float mu_s[2][9], rs_s[2][9];

    const int fastA = g_fastA;

    for (int e = tid; e < 9 * 36; e += 128) {
        int pos = e / 36, c4 = e - pos * 36;
        int i = pos / 3, j = pos - 3 * (pos / 3);
        int hh = refl(h - 1 + i), ww = refl(w - 1 + j);
        ((float4*)win[half][pos])[c4] =
            ((const float4*)(g_PROJT + (hh * 64 + ww) * 144))[c4];
    }
    float u9[9];
    #pragma unroll
    for (int pos = 0; pos < 9; pos++) {
        int i = pos / 3, j = pos % 3;
        int hh = refl(h - 1 + i), ww = refl(w - 1 + j);
        u9[pos] = g_XCT[(hh * 64 + ww) * 128 + d];
    }
    __syncthreads();

    constexpr int POS[4][9] = {
        {0,1,2,3,4,5,6,7,8},
        {0,3,6,1,4,7,2,5,8},
        {8,7,6,5,4,3,2,1,0},
        {8,5,2,7,4,1,6,3,0}};
    constexpr int PKB[4] = {0, 72, 36, 108};

    float yw[9];
    #pragma unroll
    for (int t = 0; t < 9; t++) yw[t] = 0.f;

    #pragma unroll
    for (int k = 0; k < 4; k++) {
        int kd = k * 128 + d;
        float4 dw = __ldg((const float4*)(dtw + kd * 4));
        float db = __ldg(dtb + kd);
        float Dv = __ldg(Dsp + kd);
        float AL0 = g_ALc[kd * 16];
        float delta[9];
        #pragma unroll
        for (int l = 0; l < 9; l++) {
            float4 xr = *(const float4*)&win[half][POS[k][l]][PKB[k]];
            float s = db;
            s = fmaf(dw.x, xr.x, s); s = fmaf(dw.y, xr.y, s);
            s = fmaf(dw.z, xr.z, s); s = fmaf(dw.w, xr.w, s);
            delta[l] = softplusf(s);
        }
        ull hp[8];
        #pragma unroll
        for (int j = 0; j < 8; j++) hp[j] = 0ull;
        #pragma unroll
        for (int l = 0; l < 9; l++) {
            const int pos = POS[k][l];
            float dl = delta[l];
            float du = dl * u9[pos];
            ull dup = pack2(du, du);
            const ull* Bp = (const ull*)&win[half][pos][PKB[k] + 4];
            const ull* Cp = (const ull*)&win[half][pos][PKB[k] + 20];
            ull yp = 0ull;
            if (fastA) {
                float r  = ex2f_fast(dl * AL0);
                float r2 = r * r;
                ull rr  = pack2(r2, r2);
                ull dAp = pack2(r, r2);
                #pragma unroll
                for (int j = 0; j < 8; j++) {
                    if (j) dAp = mul2(dAp, rr);
                    hp[j] = fma2(hp[j], dAp, mul2(dup, Bp[j]));
                    yp = fma2(hp[j], Cp[j], yp);
                }
            } else {
                #pragma unroll
                for (int j = 0; j < 8; j++) {
                    float2 al = *(const float2*)(g_ALc + kd * 16 + 2 * j);
                    ull dAp = pack2(ex2f_fast(dl * al.x), ex2f_fast(dl * al.y));
                    hp[j] = fma2(hp[j], dAp, mul2(dup, Bp[j]));
                    yp = fma2(hp[j], Cp[j], yp);
                }
            }
            float ylo, yhi; unpack2(yp, ylo, yhi);
            yw[pos] += fmaf(Dv, u9[pos], ylo + yhi);
        }
    }

    int warp = tid >> 5, lane = tid & 31;
    #pragma unroll
    for (int pos = 0; pos < 9; pos++) {
        float v = yw[pos], q = v * v;
        #pragma unroll
        for (int off = 16; off > 0; off >>= 1) {
            v += __shfl_xor_sync(0xffffffffu, v, off);
            q += __shfl_xor_sync(0xffffffffu, q, off);
        }
        if (lane == 0) { redS[half][pos][warp] = v; redQ[half][pos][warp] = q; }
    }
    __syncthreads();
    if (tid < 9) {
        float s = redS[half][tid][0] + redS[half][tid][1] + redS[half][tid][2] + redS[half][tid][3];
        float q = redQ[half][tid][0] + redQ[half][tid][1] + redQ[half][tid][2] + redQ[half][tid][3];
        float mu = s * (1.f / 128.f);
        float var = q * (1.f / 128.f) - mu * mu;
        mu_s[half][tid] = mu;
        rs_s[half][tid] = rsqrtf(var + 1e-5f);
    }
    __syncthreads();
    float gg = ong[d], bb = onb[d];
    #pragma unroll
    for (int pos = 0; pos < 9; pos++)
        g_YN[p * 1152 + pos * 128 + d] =
            (yw[pos] - mu_s[half][pos]) * rs_s[half][pos] * gg + bb;
}

// ---------------- K5: addconv GEMM v3: 4px x 4c; grid (64, 4 splits), 256 thr ----------------
// block: 64 px x 64 c = 16 pxg x 16 cg4, K-slice 288
__global__ void __launch_bounds__(256) k_addconv() {
    __shared__ __align__(16) float ynT[32][68];   // [k-local][px]
    __shared__ __align__(16) ull wsd[32][64];     // dup weight pairs [k][c]
    const int tid = threadIdx.x;
    const int pxg = tid & 15;
    const int cg4 = tid >> 4;          // 0..15
    const int p0 = blockIdx.x * 64;
    const int split = blockIdx.y;
    const int kb0 = split * 288;

    ull acc[2][4];
    #pragma unroll
    for (int i = 0; i < 2; i++)
        #pragma unroll
        for (int j = 0; j < 4; j++) acc[i][j] = 0ull;

    for (int kt = 0; kt < 288; kt += 32) {
        __syncthreads();
        for (int e = tid; e < 2048; e += 256) {
            int k = e & 31, px = e >> 5;
            ynT[k][px] = g_YN[(p0 + px) * 1152 + kb0 + kt + k];
        }
        for (int e = tid; e < 2048; e += 256) {
            int k = e & 31, c = e >> 5;
            float wv = g_WT[(kb0 + kt + k) * 64 + c];
            wsd[k][c] = pack2(wv, wv);
        }
        __syncthreads();
        #pragma unroll
        for (int k = 0; k < 32; k++) {
            longlong2 xq = *(const longlong2*)&ynT[k][pxg * 4];
            ull xp0 = (ull)xq.x, xp1 = (ull)xq.y;
            longlong2 wq0 = *(const longlong2*)&wsd[k][cg4 * 4];
            longlong2 wq1 = *(const longlong2*)&wsd[k][cg4 * 4 + 2];
            ull w0 = (ull)wq0.x, w1 = (ull)wq0.y, w2 = (ull)wq1.x, w3 = (ull)wq1.y;
            acc[0][0] = fma2(xp0, w0, acc[0][0]); acc[1][0] = fma2(xp1, w0, acc[1][0]);
            acc[0][1] = fma2(xp0, w1, acc[0][1]); acc[1][1] = fma2(xp1, w1, acc[1][1]);
            acc[0][2] = fma2(xp0, w2, acc[0][2]); acc[1][2] = fma2(xp1, w2, acc[1][2]);
            acc[0][3] = fma2(xp0, w3, acc[0][3]); acc[1][3] = fma2(xp1, w3, acc[1][3]);
        }
    }
    float* base = g_CORE + split * 262144;
    const int c0 = cg4 * 4;
    #pragma unroll
    for (int j = 0; j < 4; j++) {
        float v0, v1, v2, v3;
        unpack2(acc[0][j], v0, v1);
        unpack2(acc[1][j], v2, v3);
        base[(p0 + pxg * 4 + 0) * 64 + c0 + j] = v0;
        base[(p0 + pxg * 4 + 1) * 64 + c0 + j] = v1;
        base[(p0 + pxg * 4 + 2) * 64 + c0 + j] = v2;
        base[(p0 + pxg * 4 + 3) * 64 + c0 + j] = v3;
    }
}

// ---------------- K6: gate + out_proj + skip (16 px/block) ----------------
__global__ void __launch_bounds__(256) k_epilogue(
    const float* __restrict__ x, const float* __restrict__ acb,
    const float* __restrict__ skip_b, float* __restrict__ out) {
    __shared__ float ov[16][65], xv[16][65], zsm[16][65];
    __shared__ float wo[64][65], ws[64][65];
    const int tid = threadIdx.x;
    const int o = tid & 63, pg = tid >> 6;
    const int p0 = blockIdx.x * 16;

    for (int e = tid; e < 4096; e += 256) {
        int c = e >> 6, oo = e & 63;
        wo[c][oo] = g_WoT[e];
        ws[c][oo] = g_WsT[e];
    }
    #pragma unroll
    for (int i = 0; i < 4; i++) {
        int idx = tid + i * 256;
        int px2 = idx & 15, o2 = idx >> 4;
        zsm[px2][o2] = g_Zp[o2 * 4096 + p0 + px2];
    }
    __syncthreads();
    float acbv = __ldg(acb + o);
    #pragma unroll
    for (int i = 0; i < 4; i++) {
        int px = pg * 4 + i;
        int p = p0 + px;
        float core = g_CORE[p * 64 + o] + g_CORE[262144 + p * 64 + o]
                   + g_CORE[524288 + p * 64 + o] + g_CORE[786432 + p * 64 + o] + acbv;
        ov[px][o] = core * siluf(zsm[px][o]);
        xv[px][o] = x[p * 64 + o];
    }
    __syncthreads();
    float acc[4];
    float sb = __ldg(skip_b + o);
    #pragma unroll
    for (int i = 0; i < 4; i++) acc[i] = sb;
    #pragma unroll 4
    for (int c = 0; c < 64; c++) {
        float wov = wo[c][o], wsv = ws[c][o];
        #pragma unroll
        for (int i = 0; i < 4; i++) {
            int px = pg * 4 + i;
            acc[i] = fmaf(ov[px][c], wov, acc[i]);
            acc[i] = fmaf(xv[px][c], wsv, acc[i]);
        }
    }
    #pragma unroll
    for (int i = 0; i < 4; i++)
        out[(p0 + pg * 4 + i) * 64 + o] = acc[i];
}

// ---------------- launch ----------------
extern "C" void kernel_launch(void* const* d_in, const int* in_sizes, int n_in,
                              void* d_out, int out_size) {
    const float* x          = (const float*)d_in[0];
    const float* in_norm_g  = (const float*)d_in[1];
    const float* in_norm_b  = (const float*)d_in[2];
    const float* in_proj_w  = (const float*)d_in[3];
    const float* conv_w     = (const float*)d_in[4];
    const float* conv_b     = (const float*)d_in[5];
    const float* x_proj_w   = (const float*)d_in[6];
    const float* dt_w       = (const float*)d_in[7];
    const float* dt_b       = (const float*)d_in[8];
    const float* A_logs     = (const float*)d_in[9];
    const float* Ds         = (const float*)d_in[10];
    const float* out_norm_g = (const float*)d_in[11];
    const float* out_norm_b = (const float*)d_in[12];
    const float* addconv_w  = (const float*)d_in[13];
    const float* addconv_b  = (const float*)d_in[14];
    const float* skip_w     = (const float*)d_in[15];
    const float* skip_b     = (const float*)d_in[16];
    const float* out_proj_w = (const float*)d_in[17];
    float* out = (float*)d_out;

    k_pre<<<352, 256>>>(A_logs, addconv_w, out_proj_w, skip_w);
    k_ln<<<512, 256>>>(x, in_norm_g, in_norm_b);
    k_inproj<<<dim3(128, 6), 256>>>(in_proj_w);
    k_conv<<<512, 256>>>(conv_w, conv_b);
    k_xproj<<<dim3(64, 4), 144>>>(x_proj_w);
    k_scan<<<2048, 256>>>(dt_w, dt_b, Ds, out_norm_g, out_norm_b);
    k_addconv<<<dim3(64, 4), 256>>>();
    k_epilogue<<<256, 256>>>(x, addconv_b, skip_b, out);
}

// round 10
// speedup vs baseline: 1.2605x; 1.1955x over previous
#include <cuda_runtime.h>
#include <math.h>

#define LOG2E 1.4426950408889634f
typedef unsigned long long ull;

// ---------------- scratch (device globals; no allocation) ----------------
__device__ float g_XN  [4096 * 64];       // layernormed input [p][c]
__device__ float g_XI  [128 * 4096];      // in_proj xi, planar [d][hw]
__device__ float g_Zp  [64 * 4096];       // z gate, planar [o][p]
__device__ float g_XCT [4096 * 128];      // conv+silu output, pixel-major [p][d]
__device__ float g_PROJT[4096 * 144];     // x_proj output, pixel-major [p][144]
__device__ float g_YN  [4096 * 1152];     // post-LN window features [p][pos*128+d]
__device__ float g_CORE[4 * 4096 * 64];   // addconv partials (split-k=4) [s][p][o]
__device__ float g_ALc [512 * 16];        // -exp(A_logs) * log2e
__device__ float g_WT  [1152 * 64];       // addconv_w transposed [pos*128+d][o]
__device__ float g_WoT [64 * 64];         // out_proj_w^T [c][o]
__device__ float g_WsT [64 * 64];         // skip_w^T [c][o]
__device__ int   g_fastA = 1;             // A has geometric structure (sticky)

// ---------------- helpers ----------------
__device__ __forceinline__ float ex2f_fast(float x) {
    float y; asm("ex2.approx.f32 %0, %1;" : "=f"(y) : "f"(x)); return y;
}
__device__ __forceinline__ float softplusf(float x) {
    return x > 15.f ? x : __logf(1.f + __expf(x));
}
__device__ __forceinline__ float siluf(float x) {
    return x / (1.f + __expf(-x));
}
__device__ __forceinline__ int refl(int v) {
    return v < 0 ? -v : (v > 63 ? 126 - v : v);
}
__device__ __forceinline__ ull pack2(float a, float b) {
    ull r; asm("mov.b64 %0, {%1,%2};" : "=l"(r) : "f"(a), "f"(b)); return r;
}
__device__ __forceinline__ void unpack2(ull v, float& a, float& b) {
    asm("mov.b64 {%0,%1}, %2;" : "=f"(a), "=f"(b) : "l"(v));
}
__device__ __forceinline__ ull fma2(ull a, ull b, ull c) {
    ull d; asm("fma.rn.f32x2 %0, %1, %2, %3;" : "=l"(d) : "l"(a), "l"(b), "l"(c)); return d;
}
__device__ __forceinline__ ull mul2(ull a, ull b) {
    ull d; asm("mul.rn.f32x2 %0, %1, %2;" : "=l"(d) : "l"(a), "l"(b)); return d;
}

// ---------------- K1: layernorm + precompute (merged, 512 blocks) ----------------
__global__ void __launch_bounds__(256) k_lnpre(
    const float* __restrict__ x, const float* __restrict__ g,
    const float* __restrict__ b,
    const float* __restrict__ A_logs, const float* __restrict__ addconv_w,
    const float* __restrict__ out_proj_w, const float* __restrict__ skip_w) {
    // --- LN part (all 512 blocks, warp per pixel) ---
    int warp = threadIdx.x >> 5, lane = threadIdx.x & 31;
    int p = blockIdx.x * 8 + warp;
    float x0 = x[p * 64 + lane], x1 = x[p * 64 + lane + 32];
    float s = x0 + x1;
    #pragma unroll
    for (int off = 16; off > 0; off >>= 1) s += __shfl_xor_sync(0xffffffffu, s, off);
    float mu = s * (1.f / 64.f);
    float d0 = x0 - mu, d1 = x1 - mu;
    float q = d0 * d0 + d1 * d1;
    #pragma unroll
    for (int off = 16; off > 0; off >>= 1) q += __shfl_xor_sync(0xffffffffu, q, off);
    float rstd = rsqrtf(q * (1.f / 64.f) + 1e-5f);
    g_XN[p * 64 + lane]      = d0 * rstd * g[lane]      + b[lane];
    g_XN[p * 64 + lane + 32] = d1 * rstd * g[lane + 32] + b[lane + 32];

    // --- precompute part (first 90112 threads) ---
    int idx = blockIdx.x * 256 + threadIdx.x;
    if (idx < 73728) {
        int o = idx & 63; int rest = idx >> 6;
        int d = rest & 127; int pos = rest >> 7;
        g_WT[idx] = addconv_w[o * 1152 + d * 9 + pos];
    } else if (idx < 73728 + 8192) {
        int j = idx - 73728;
        float e = expf(A_logs[j]);
        g_ALc[j] = -e * LOG2E;
        int n = j & 15;
        float e0 = expf(A_logs[j & ~15]);
        if (fabsf(e - (float)(n + 1) * e0) > 1e-4f * fmaxf(e, 1e-6f))
            atomicAnd(&g_fastA, 0);
    } else if (idx < 73728 + 8192 + 4096) {
        int j = idx - 73728 - 8192;
        int o = j & 63, c = j >> 6;
        g_WoT[j] = out_proj_w[o * 64 + c];
    } else if (idx < 73728 + 8192 + 8192) {
        int j = idx - 73728 - 8192 - 4096;
        int o = j & 63, c = j >> 6;
        g_WsT[j] = skip_w[o * 64 + c];
    }
}

// ---------------- K2: in_proj GEMM; grid (128, 6) [R3 proven] ----------------
__global__ void __launch_bounds__(256) k_inproj(const float* __restrict__ ipw) {
    __shared__ float xs[32][65];
    __shared__ float ws[64][34];
    const int tid = threadIdx.x;
    const int warp = tid >> 5, lane = tid & 31;
    const int p0 = blockIdx.x * 32;
    const int cg = blockIdx.y * 32;
    for (int e = tid; e < 2048; e += 256) {
        int px = e >> 6, k = e & 63;
        xs[px][k] = g_XN[(p0 + px) * 64 + k];
    }
    for (int e = tid; e < 2048; e += 256) {
        int cc = e >> 6, k = e & 63;
        ws[k][cc] = ipw[(cg + cc) * 64 + k];
    }
    __syncthreads();
    ull a0 = 0ull, a1 = 0ull;
    #pragma unroll
    for (int k = 0; k < 64; k++) {
        float xv = xs[lane][k];
        ull xp = pack2(xv, xv);
        a0 = fma2(xp, *(const ull*)&ws[k][4 * warp],     a0);
        a1 = fma2(xp, *(const ull*)&ws[k][4 * warp + 2], a1);
    }
    int p = p0 + lane;
    float r0, r1, r2, r3;
    unpack2(a0, r0, r1); unpack2(a1, r2, r3);
    int c = cg + 4 * warp;
    float rv[4] = {r0, r1, r2, r3};
    #pragma unroll
    for (int j = 0; j < 4; j++) {
        int cj = c + j;
        if (cj < 128) g_XI[cj * 4096 + p] = rv[j];
        else          g_Zp[(cj - 128) * 4096 + p] = rv[j];
    }
}

// ---------------- K3: depthwise 3x3 conv [R3 proven, 512 blocks] ----------------
__global__ void __launch_bounds__(256) k_conv(
    const float* __restrict__ cw, const float* __restrict__ cb) {
    const int h  = blockIdx.x >> 3, dg = blockIdx.x & 7;
    const int tid = threadIdx.x;
    const int w = tid & 63, q = tid >> 6;
    const int d0 = dg * 16 + q * 4;
    float o[4];
    #pragma unroll
    for (int i = 0; i < 4; i++) {
        int d = d0 + i;
        float acc = __ldg(cb + d);
        #pragma unroll
        for (int ki = 0; ki < 3; ki++) {
            int hh = h + ki - 1;
            if (hh < 0 || hh > 63) continue;
            const float* row = g_XI + d * 4096 + hh * 64 + w;
            if (w > 0)  acc = fmaf(__ldg(cw + d * 9 + ki * 3 + 0), row[-1], acc);
                        acc = fmaf(__ldg(cw + d * 9 + ki * 3 + 1), row[0],  acc);
            if (w < 63) acc = fmaf(__ldg(cw + d * 9 + ki * 3 + 2), row[1],  acc);
        }
        o[i] = siluf(acc);
    }
    *(float4*)(g_XCT + (h * 64 + w) * 128 + d0) = make_float4(o[0], o[1], o[2], o[3]);
}

// ---------------- K4: x_proj GEMM v3 [R5-sub, measured 21.9us] ----------------
// block: 64 px x 36 c; thread: 4 px x 2 c; grid (64, 4), 288 thr
__global__ void __launch_bounds__(288) k_xproj(const float* __restrict__ xpw) {
    __shared__ __align__(16) float xcT[64][66];   // [k-local][px]
    __shared__ ull wsd[64][36];                   // duplicated weight pairs
    const int tid = threadIdx.x;
    const int pxg = tid & 15;        // 16 groups of 4 px
    const int cq  = tid >> 4;        // 18 groups of 2 c
    const int p0 = blockIdx.x * 64;
    const int cg = blockIdx.y * 36;

    ull acc00 = 0ull, acc01 = 0ull, acc10 = 0ull, acc11 = 0ull;

    for (int kb = 0; kb < 128; kb += 64) {
        __syncthreads();
        for (int e = tid; e < 4096; e += 288) {
            int k = e & 63, px = e >> 6;
            xcT[k][px] = g_XCT[(p0 + px) * 128 + kb + k];
        }
        for (int e = tid; e < 2304; e += 288) {
            int k = e & 63, c = e >> 6;
            float wv = xpw[(cg + c) * 128 + kb + k];
            wsd[k][c] = pack2(wv, wv);
        }
        __syncthreads();
        #pragma unroll 4
        for (int k = 0; k < 64; k++) {
            ull xp0 = *(const ull*)&xcT[k][pxg * 4];
            ull xp1 = *(const ull*)&xcT[k][pxg * 4 + 2];
            ull w0 = wsd[k][cq * 2];
            ull w1 = wsd[k][cq * 2 + 1];
            acc00 = fma2(xp0, w0, acc00);
            acc01 = fma2(xp0, w1, acc01);
            acc10 = fma2(xp1, w0, acc10);
            acc11 = fma2(xp1, w1, acc11);
        }
    }
    float v[2][4];
    unpack2(acc00, v[0][0], v[0][1]);
    unpack2(acc10, v[0][2], v[0][3]);
    unpack2(acc01, v[1][0], v[1][1]);
    unpack2(acc11, v[1][2], v[1][3]);
    #pragma unroll
    for (int j = 0; j < 2; j++)
        #pragma unroll
        for (int i = 0; i < 4; i++)
            g_PROJT[(p0 + pxg * 4 + i) * 144 + cg + cq * 2 + j] = v[j][i];
}

// ---------------- K5: selective scan + combine + per-position LN [R3 proven] ----------------
__global__ void __launch_bounds__(256) k_scan(
    const float* __restrict__ dtw, const float* __restrict__ dtb,
    const float* __restrict__ Dsp, const float* __restrict__ ong,
    const float* __restrict__ onb) {
    const int half = threadIdx.x >> 7;
    const int tid  = threadIdx.x & 127;
    const int p = blockIdx.x * 2 + half;
    const int h = p >> 6, w = p & 63;
    const int d = tid;
    __shared__ __align__(16) float win[2][9][144];
    __shared__ float redS[2][9][4], redQ[2][9][4];
    __shared__ float mu_s[2][9], rs_s[2][9];

    const int fastA = g_fastA;

    for (int e = tid; e < 9 * 36; e += 128) {
        int pos = e / 36, c4 = e - pos * 36;
        int i = pos / 3, j = pos - 3 * (pos / 3);
        int hh = refl(h - 1 + i), ww = refl(w - 1 + j);
        ((float4*)win[half][pos])[c4] =
            ((const float4*)(g_PROJT + (hh * 64 + ww) * 144))[c4];
    }
    float u9[9];
    #pragma unroll
    for (int pos = 0; pos < 9; pos++) {
        int i = pos / 3, j = pos % 3;
        int hh = refl(h - 1 + i), ww = refl(w - 1 + j);
        u9[pos] = g_XCT[(hh * 64 + ww) * 128 + d];
    }
    __syncthreads();

    constexpr int POS[4][9] = {
        {0,1,2,3,4,5,6,7,8},
        {0,3,6,1,4,7,2,5,8},
        {8,7,6,5,4,3,2,1,0},
        {8,5,2,7,4,1,6,3,0}};
    constexpr int PKB[4] = {0, 72, 36, 108};

    float yw[9];
    #pragma unroll
    for (int t = 0; t < 9; t++) yw[t] = 0.f;

    #pragma unroll
    for (int k = 0; k < 4; k++) {
        int kd = k * 128 + d;
        float4 dw = __ldg((const float4*)(dtw + kd * 4));
        float db = __ldg(dtb + kd);
        float Dv = __ldg(Dsp + kd);
        float AL0 = g_ALc[kd * 16];
        float delta[9];
        #pragma unroll
        for (int l = 0; l < 9; l++) {
            float4 xr = *(const float4*)&win[half][POS[k][l]][PKB[k]];
            float s = db;
            s = fmaf(dw.x, xr.x, s); s = fmaf(dw.y, xr.y, s);
            s = fmaf(dw.z, xr.z, s); s = fmaf(dw.w, xr.w, s);
            delta[l] = softplusf(s);
        }
        ull hp[8];
        #pragma unroll
        for (int j = 0; j < 8; j++) hp[j] = 0ull;
        #pragma unroll
        for (int l = 0; l < 9; l++) {
            const int pos = POS[k][l];
            float dl = delta[l];
            float du = dl * u9[pos];
            ull dup = pack2(du, du);
            const ull* Bp = (const ull*)&win[half][pos][PKB[k] + 4];
            const ull* Cp = (const ull*)&win[half][pos][PKB[k] + 20];
            ull yp = 0ull;
            if (fastA) {
                float r  = ex2f_fast(dl * AL0);
                float r2 = r * r;
                ull rr  = pack2(r2, r2);
                ull dAp = pack2(r, r2);
                #pragma unroll
                for (int j = 0; j < 8; j++) {
                    if (j) dAp = mul2(dAp, rr);
                    hp[j] = fma2(hp[j], dAp, mul2(dup, Bp[j]));
                    yp = fma2(hp[j], Cp[j], yp);
                }
            } else {
                #pragma unroll
                for (int j = 0; j < 8; j++) {
                    float2 al = *(const float2*)(g_ALc + kd * 16 + 2 * j);
                    ull dAp = pack2(ex2f_fast(dl * al.x), ex2f_fast(dl * al.y));
                    hp[j] = fma2(hp[j], dAp, mul2(dup, Bp[j]));
                    yp = fma2(hp[j], Cp[j], yp);
                }
            }
            float ylo, yhi; unpack2(yp, ylo, yhi);
            yw[pos] += fmaf(Dv, u9[pos], ylo + yhi);
        }
    }

    int warp = tid >> 5, lane = tid & 31;
    #pragma unroll
    for (int pos = 0; pos < 9; pos++) {
        float v = yw[pos], q = v * v;
        #pragma unroll
        for (int off = 16; off > 0; off >>= 1) {
            v += __shfl_xor_sync(0xffffffffu, v, off);
            q += __shfl_xor_sync(0xffffffffu, q, off);
        }
        if (lane == 0) { redS[half][pos][warp] = v; redQ[half][pos][warp] = q; }
    }
    __syncthreads();
    if (tid < 9) {
        float s = redS[half][tid][0] + redS[half][tid][1] + redS[half][tid][2] + redS[half][tid][3];
        float q = redQ[half][tid][0] + redQ[half][tid][1] + redQ[half][tid][2] + redQ[half][tid][3];
        float mu = s * (1.f / 128.f);
        float var = q * (1.f / 128.f) - mu * mu;
        mu_s[half][tid] = mu;
        rs_s[half][tid] = rsqrtf(var + 1e-5f);
    }
    __syncthreads();
    float gg = ong[d], bb = onb[d];
    #pragma unroll
    for (int pos = 0; pos < 9; pos++)
        g_YN[p * 1152 + pos * 128 + d] =
            (yw[pos] - mu_s[half][pos]) * rs_s[half][pos] * gg + bb;
}

// ---------------- K6: addconv GEMM split-k=4 [R3 proven, grid (128,4)] ----------------
__global__ void __launch_bounds__(256) k_addconv() {
    __shared__ float As[32][33];
    __shared__ float Bs[32][68];
    const int tid = threadIdx.x;
    const int warp = tid >> 5, lane = tid & 31;
    const int p0 = blockIdx.x * 32;
    const int split = blockIdx.y;
    const int kb = split * 288;
    ull acc[4] = {0ull, 0ull, 0ull, 0ull};
    for (int kt = 0; kt < 288; kt += 32) {
        __syncthreads();
        for (int e = tid; e < 1024; e += 256) {
            int px = e >> 5, k = e & 31;
            As[px][k] = g_YN[(p0 + px) * 1152 + kb + kt + k];
        }
        for (int e = tid; e < 2048; e += 256) {
            int k = e >> 6, c = e & 63;
            Bs[k][c] = g_WT[(kb + kt + k) * 64 + c];
        }
        __syncthreads();
        #pragma unroll
        for (int k = 0; k < 32; k++) {
            float a = As[lane][k];
            ull ap = pack2(a, a);
            #pragma unroll
            for (int j = 0; j < 4; j++)
                acc[j] = fma2(ap, *(const ull*)&Bs[k][8 * warp + 2 * j], acc[j]);
        }
    }
    int p = p0 + lane;
    float r0, r1, r2, r3, r4, r5, r6, r7;
    unpack2(acc[0], r0, r1); unpack2(acc[1], r2, r3);
    unpack2(acc[2], r4, r5); unpack2(acc[3], r6, r7);
    float* dst = g_CORE + split * 262144 + p * 64 + 8 * warp;
    *(float4*)dst       = make_float4(r0, r1, r2, r3);
    *(float4*)(dst + 4) = make_float4(r4, r5, r6, r7);
}

// ---------------- K7: gate + out_proj + skip [R3 proven] ----------------
__global__ void __launch_bounds__(256) k_epilogue(
    const float* __restrict__ x, const float* __restrict__ acb,
    const float* __restrict__ skip_b, float* __restrict__ out) {
    __shared__ float ov[16][65], xv[16][65], zsm[16][65];
    __shared__ float wo[64][65], ws[64][65];
    const int tid = threadIdx.x;
    const int o = tid & 63, pg = tid >> 6;
    const int p0 = blockIdx.x * 16;

    for (int e = tid; e < 4096; e += 256) {
        int c = e >> 6, oo = e & 63;
        wo[c][oo] = g_WoT[e];
        ws[c][oo] = g_WsT[e];
    }
    #pragma unroll
    for (int i = 0; i < 4; i++) {
        int idx = tid + i * 256;
        int px2 = idx & 15, o2 = idx >> 4;
        zsm[px2][o2] = g_Zp[o2 * 4096 + p0 + px2];
    }
    __syncthreads();
    float acbv = __ldg(acb + o);
    #pragma unroll
    for (int i = 0; i < 4; i++) {
        int px = pg * 4 + i;
        int p = p0 + px;
        float core = g_CORE[p * 64 + o] + g_CORE[262144 + p * 64 + o]
                   + g_CORE[524288 + p * 64 + o] + g_CORE[786432 + p * 64 + o] + acbv;
        ov[px][o] = core * siluf(zsm[px][o]);
        xv[px][o] = x[p * 64 + o];
    }
    __syncthreads();
    float acc[4];
    float sb = __ldg(skip_b + o);
    #pragma unroll
    for (int i = 0; i < 4; i++) acc[i] = sb;
    #pragma unroll 4
    for (int c = 0; c < 64; c++) {
        float wov = wo[c][o], wsv = ws[c][o];
        #pragma unroll
        for (int i = 0; i < 4; i++) {
            int px = pg * 4 + i;
            acc[i] = fmaf(ov[px][c], wov, acc[i]);
            acc[i] = fmaf(xv[px][c], wsv, acc[i]);
        }
    }
    #pragma unroll
    for (int i = 0; i < 4; i++)
        out[(p0 + pg * 4 + i) * 64 + o] = acc[i];
}

// ---------------- launch ----------------
extern "C" void kernel_launch(void* const* d_in, const int* in_sizes, int n_in,
                              void* d_out, int out_size) {
    const float* x          = (const float*)d_in[0];
    const float* in_norm_g  = (const float*)d_in[1];
    const float* in_norm_b  = (const float*)d_in[2];
    const float* in_proj_w  = (const float*)d_in[3];
    const float* conv_w     = (const float*)d_in[4];
    const float* conv_b     = (const float*)d_in[5];
    const float* x_proj_w   = (const float*)d_in[6];
    const float* dt_w       = (const float*)d_in[7];
    const float* dt_b       = (const float*)d_in[8];
    const float* A_logs     = (const float*)d_in[9];
    const float* Ds         = (const float*)d_in[10];
    const float* out_norm_g = (const float*)d_in[11];
    const float* out_norm_b = (const float*)d_in[12];
    const float* addconv_w  = (const float*)d_in[13];
    const float* addconv_b  = (const float*)d_in[14];
    const float* skip_w     = (const float*)d_in[15];
    const float* skip_b     = (const float*)d_in[16];
    const float* out_proj_w = (const float*)d_in[17];
    float* out = (float*)d_out;

    k_lnpre<<<512, 256>>>(x, in_norm_g, in_norm_b,
                          A_logs, addconv_w, out_proj_w, skip_w);
    k_inproj<<<dim3(128, 6), 256>>>(in_proj_w);
    k_conv<<<512, 256>>>(conv_w, conv_b);
    k_xproj<<<dim3(64, 4), 288>>>(x_proj_w);
    k_scan<<<2048, 256>>>(dt_w, dt_b, Ds, out_norm_g, out_norm_b);
    k_addconv<<<dim3(128, 4), 256>>>();
    k_epilogue<<<256, 256>>>(x, addconv_b, skip_b, out);
}

// round 11
// speedup vs baseline: 1.2660x; 1.0044x over previous
#include <cuda_runtime.h>
#include <math.h>

#define LOG2E 1.4426950408889634f
typedef unsigned long long ull;

// ---------------- scratch (device globals; no allocation) ----------------
__device__ float g_XN  [4096 * 64];       // layernormed input [p][c]
__device__ float g_XI  [128 * 4096];      // in_proj xi, planar [d][hw]
__device__ float g_Zp  [64 * 4096];       // z gate, planar [o][p]
__device__ float g_XCT [4096 * 128];      // conv+silu output, pixel-major [p][d]
__device__ float g_PROJT[4096 * 144];     // x_proj output, pixel-major [p][144]
__device__ float g_YN  [4096 * 1152];     // post-LN window features [p][pos*128+d]
__device__ float g_CORE[4 * 4096 * 64];   // addconv partials (split-k=4) [s][p][o]
__device__ float g_ALc [512 * 16];        // -exp(A_logs) * log2e
__device__ float g_WT  [1152 * 64];       // addconv_w transposed [pos*128+d][o]
__device__ float g_WoT [64 * 64];         // out_proj_w^T [c][o]
__device__ float g_WsT [64 * 64];         // skip_w^T [c][o]
__device__ int   g_fastA = 1;             // A has geometric structure (sticky)

// ---------------- helpers ----------------
__device__ __forceinline__ float ex2f_fast(float x) {
    float y; asm("ex2.approx.f32 %0, %1;" : "=f"(y) : "f"(x)); return y;
}
__device__ __forceinline__ float softplusf(float x) {
    return x > 15.f ? x : __logf(1.f + __expf(x));
}
__device__ __forceinline__ float siluf(float x) {
    return x / (1.f + __expf(-x));
}
__device__ __forceinline__ int refl(int v) {
    return v < 0 ? -v : (v > 63 ? 126 - v : v);
}
__device__ __forceinline__ ull pack2(float a, float b) {
    ull r; asm("mov.b64 %0, {%1,%2};" : "=l"(r) : "f"(a), "f"(b)); return r;
}
__device__ __forceinline__ void unpack2(ull v, float& a, float& b) {
    asm("mov.b64 {%0,%1}, %2;" : "=f"(a), "=f"(b) : "l"(v));
}
__device__ __forceinline__ ull fma2(ull a, ull b, ull c) {
    ull d; asm("fma.rn.f32x2 %0, %1, %2, %3;" : "=l"(d) : "l"(a), "l"(b), "l"(c)); return d;
}
__device__ __forceinline__ ull mul2(ull a, ull b) {
    ull d; asm("mul.rn.f32x2 %0, %1, %2;" : "=l"(d) : "l"(a), "l"(b)); return d;
}

// ---------------- K0: precompute ----------------
__global__ void k_pre(const float* __restrict__ A_logs,
                      const float* __restrict__ addconv_w,
                      const float* __restrict__ out_proj_w,
                      const float* __restrict__ skip_w) {
    int idx = blockIdx.x * 256 + threadIdx.x;
    if (idx < 73728) {
        int o = idx & 63; int rest = idx >> 6;
        int d = rest & 127; int pos = rest >> 7;
        g_WT[idx] = addconv_w[o * 1152 + d * 9 + pos];
    } else if (idx < 73728 + 8192) {
        int j = idx - 73728;
        float e = expf(A_logs[j]);
        g_ALc[j] = -e * LOG2E;
        int n = j & 15;
        float e0 = expf(A_logs[j & ~15]);
        if (fabsf(e - (float)(n + 1) * e0) > 1e-4f * fmaxf(e, 1e-6f))
            atomicAnd(&g_fastA, 0);
    } else if (idx < 73728 + 8192 + 4096) {
        int j = idx - 73728 - 8192;
        int o = j & 63, c = j >> 6;
        g_WoT[j] = out_proj_w[o * 64 + c];
    } else if (idx < 73728 + 8192 + 8192) {
        int j = idx - 73728 - 8192 - 4096;
        int o = j & 63, c = j >> 6;
        g_WsT[j] = skip_w[o * 64 + c];
    }
}

// ---------------- K1a: layernorm ----------------
__global__ void __launch_bounds__(256) k_ln(
    const float* __restrict__ x, const float* __restrict__ g,
    const float* __restrict__ b) {
    int warp = threadIdx.x >> 5, lane = threadIdx.x & 31;
    int p = blockIdx.x * 8 + warp;
    float x0 = x[p * 64 + lane], x1 = x[p * 64 + lane + 32];
    float s = x0 + x1;
    #pragma unroll
    for (int off = 16; off > 0; off >>= 1) s += __shfl_xor_sync(0xffffffffu, s, off);
    float mu = s * (1.f / 64.f);
    float d0 = x0 - mu, d1 = x1 - mu;
    float q = d0 * d0 + d1 * d1;
    #pragma unroll
    for (int off = 16; off > 0; off >>= 1) q += __shfl_xor_sync(0xffffffffu, q, off);
    float rstd = rsqrtf(q * (1.f / 64.f) + 1e-5f);
    g_XN[p * 64 + lane]      = d0 * rstd * g[lane]      + b[lane];
    g_XN[p * 64 + lane + 32] = d1 * rstd * g[lane + 32] + b[lane + 32];
}

// ---------------- K1b: in_proj GEMM; grid (128, 6) ----------------
__global__ void __launch_bounds__(256) k_inproj(const float* __restrict__ ipw) {
    __shared__ float xs[32][65];
    __shared__ float ws[64][34];
    const int tid = threadIdx.x;
    const int warp = tid >> 5, lane = tid & 31;
    const int p0 = blockIdx.x * 32;
    const int cg = blockIdx.y * 32;
    for (int e = tid; e < 2048; e += 256) {
        int px = e >> 6, k = e & 63;
        xs[px][k] = g_XN[(p0 + px) * 64 + k];
    }
    for (int e = tid; e < 2048; e += 256) {
        int cc = e >> 6, k = e & 63;
        ws[k][cc] = ipw[(cg + cc) * 64 + k];
    }
    __syncthreads();
    ull a0 = 0ull, a1 = 0ull;
    #pragma unroll
    for (int k = 0; k < 64; k++) {
        float xv = xs[lane][k];
        ull xp = pack2(xv, xv);
        a0 = fma2(xp, *(const ull*)&ws[k][4 * warp],     a0);
        a1 = fma2(xp, *(const ull*)&ws[k][4 * warp + 2], a1);
    }
    int p = p0 + lane;
    float r0, r1, r2, r3;
    unpack2(a0, r0, r1); unpack2(a1, r2, r3);
    int c = cg + 4 * warp;
    float rv[4] = {r0, r1, r2, r3};
    #pragma unroll
    for (int j = 0; j < 4; j++) {
        int cj = c + j;
        if (cj < 128) g_XI[cj * 4096 + p] = rv[j];
        else          g_Zp[(cj - 128) * 4096 + p] = rv[j];
    }
}

// ---------------- K2: depthwise 3x3 conv (zero pad) + bias + silu ----------------
__global__ void __launch_bounds__(256) k_conv(
    const float* __restrict__ cw, const float* __restrict__ cb) {
    const int h  = blockIdx.x >> 3, dg = blockIdx.x & 7;
    const int tid = threadIdx.x;
    const int w = tid & 63, q = tid >> 6;
    const int d0 = dg * 16 + q * 4;
    float o[4];
    #pragma unroll
    for (int i = 0; i < 4; i++) {
        int d = d0 + i;
        float acc = __ldg(cb + d);
        #pragma unroll
        for (int ki = 0; ki < 3; ki++) {
            int hh = h + ki - 1;
            if (hh < 0 || hh > 63) continue;
            const float* row = g_XI + d * 4096 + hh * 64 + w;
            if (w > 0)  acc = fmaf(__ldg(cw + d * 9 + ki * 3 + 0), row[-1], acc);
                        acc = fmaf(__ldg(cw + d * 9 + ki * 3 + 1), row[0],  acc);
            if (w < 63) acc = fmaf(__ldg(cw + d * 9 + ki * 3 + 2), row[1],  acc);
        }
        o[i] = siluf(acc);
    }
    *(float4*)(g_XCT + (h * 64 + w) * 128 + d0) = make_float4(o[0], o[1], o[2], o[3]);
}

// ---------------- K3: x_proj GEMM v3 (measured 21.9us): grid (64,4), 288 thr ----------------
__global__ void __launch_bounds__(288) k_xproj(const float* __restrict__ xpw) {
    __shared__ __align__(16) float xcT[64][66];   // [k-local][px]
    __shared__ ull wsd[64][36];                   // duplicated weight pairs
    const int tid = threadIdx.x;
    const int pxg = tid & 15;        // 16 groups of 4 px
    const int cq  = tid >> 4;        // 18 groups of 2 c
    const int p0 = blockIdx.x * 64;
    const int cg = blockIdx.y * 36;

    ull acc00 = 0ull, acc01 = 0ull, acc10 = 0ull, acc11 = 0ull;

    for (int kb = 0; kb < 128; kb += 64) {
        __syncthreads();
        for (int e = tid; e < 4096; e += 288) {
            int k = e & 63, px = e >> 6;
            xcT[k][px] = g_XCT[(p0 + px) * 128 + kb + k];
        }
        for (int e = tid; e < 2304; e += 288) {
            int k = e & 63, c = e >> 6;
            float wv = xpw[(cg + c) * 128 + kb + k];
            wsd[k][c] = pack2(wv, wv);
        }
        __syncthreads();
        #pragma unroll 4
        for (int k = 0; k < 64; k++) {
            ull xp0 = *(const ull*)&xcT[k][pxg * 4];
            ull xp1 = *(const ull*)&xcT[k][pxg * 4 + 2];
            ull w0 = wsd[k][cq * 2];
            ull w1 = wsd[k][cq * 2 + 1];
            acc00 = fma2(xp0, w0, acc00);
            acc01 = fma2(xp0, w1, acc01);
            acc10 = fma2(xp1, w0, acc10);
            acc11 = fma2(xp1, w1, acc11);
        }
    }
    float v[2][4];
    unpack2(acc00, v[0][0], v[0][1]);
    unpack2(acc10, v[0][2], v[0][3]);
    unpack2(acc01, v[1][0], v[1][1]);
    unpack2(acc11, v[1][2], v[1][3]);
    #pragma unroll
    for (int j = 0; j < 2; j++)
        #pragma unroll
        for (int i = 0; i < 4; i++)
            g_PROJT[(p0 + pxg * 4 + i) * 144 + cg + cq * 2 + j] = v[j][i];
}

// ---------------- K4: selective scan + combine + per-position LN (R4 proven) ----------------
__global__ void __launch_bounds__(256) k_scan(
    const float* __restrict__ dtw, const float* __restrict__ dtb,
    const float* __restrict__ Dsp, const float* __restrict__ ong,
    const float* __restrict__ onb) {
    const int half = threadIdx.x >> 7;
    const int tid  = threadIdx.x & 127;
    const int p = blockIdx.x * 2 + half;
    const int h = p >> 6, w = p & 63;
    const int d = tid;
    __shared__ __align__(16) float win[2][9][144];
    __shared__ float redS[2][9][4], redQ[2][9][4];
    __shared__ float mu_s[2][9], rs_s[2][9];

    const int fastA = g_fastA;

    for (int e = tid; e < 9 * 36; e += 128) {
        int pos = e / 36, c4 = e - pos * 36;
        int i = pos / 3, j = pos - 3 * (pos / 3);
        int hh = refl(h - 1 + i), ww = refl(w - 1 + j);
        ((float4*)win[half][pos])[c4] =
            ((const float4*)(g_PROJT + (hh * 64 + ww) * 144))[c4];
    }
    float u9[9];
    #pragma unroll
    for (int pos = 0; pos < 9; pos++) {
        int i = pos / 3, j = pos % 3;
        int hh = refl(h - 1 + i), ww = refl(w - 1 + j);
        u9[pos] = g_XCT[(hh * 64 + ww) * 128 + d];
    }
    __syncthreads();

    constexpr int POS[4][9] = {
        {0,1,2,3,4,5,6,7,8},
        {0,3,6,1,4,7,2,5,8},
        {8,7,6,5,4,3,2,1,0},
        {8,5,2,7,4,1,6,3,0}};
    constexpr int PKB[4] = {0, 72, 36, 108};

    float yw[9];
    #pragma unroll
    for (int t = 0; t < 9; t++) yw[t] = 0.f;

    #pragma unroll
    for (int k = 0; k < 4; k++) {
        int kd = k * 128 + d;
        float4 dw = __ldg((const float4*)(dtw + kd * 4));
        float db = __ldg(dtb + kd);
        float Dv = __ldg(Dsp + kd);
        float AL0 = g_ALc[kd * 16];
        float delta[9];
        #pragma unroll
        for (int l = 0; l < 9; l++) {
            float4 xr = *(const float4*)&win[half][POS[k][l]][PKB[k]];
            float s = db;
            s = fmaf(dw.x, xr.x, s); s = fmaf(dw.y, xr.y, s);
            s = fmaf(dw.z, xr.z, s); s = fmaf(dw.w, xr.w, s);
            delta[l] = softplusf(s);
        }
        ull hp[8];
        #pragma unroll
        for (int j = 0; j < 8; j++) hp[j] = 0ull;
        #pragma unroll
        for (int l = 0; l < 9; l++) {
            const int pos = POS[k][l];
            float dl = delta[l];
            float du = dl * u9[pos];
            ull dup = pack2(du, du);
            const ull* Bp = (const ull*)&win[half][pos][PKB[k] + 4];
            const ull* Cp = (const ull*)&win[half][pos][PKB[k] + 20];
            ull yp = 0ull;
            if (fastA) {
                float r  = ex2f_fast(dl * AL0);
                float r2 = r * r;
                ull rr  = pack2(r2, r2);
                ull dAp = pack2(r, r2);
                #pragma unroll
                for (int j = 0; j < 8; j++) {
                    if (j) dAp = mul2(dAp, rr);
                    hp[j] = fma2(hp[j], dAp, mul2(dup, Bp[j]));
                    yp = fma2(hp[j], Cp[j], yp);
                }
            } else {
                #pragma unroll
                for (int j = 0; j < 8; j++) {
                    float2 al = *(const float2*)(g_ALc + kd * 16 + 2 * j);
                    ull dAp = pack2(ex2f_fast(dl * al.x), ex2f_fast(dl * al.y));
                    hp[j] = fma2(hp[j], dAp, mul2(dup, Bp[j]));
                    yp = fma2(hp[j], Cp[j], yp);
                }
            }
            float ylo, yhi; unpack2(yp, ylo, yhi);
            yw[pos] += fmaf(Dv, u9[pos], ylo + yhi);
        }
    }

    int warp = tid >> 5, lane = tid & 31;
    #pragma unroll
    for (int pos = 0; pos < 9; pos++) {
        float v = yw[pos], q = v * v;
        #pragma unroll
        for (int off = 16; off > 0; off >>= 1) {
            v += __shfl_xor_sync(0xffffffffu, v, off);
            q += __shfl_xor_sync(0xffffffffu, q, off);
        }
        if (lane == 0) { redS[half][pos][warp] = v; redQ[half][pos][warp] = q; }
    }
    __syncthreads();
    if (tid < 9) {
        float s = redS[half][tid][0] + redS[half][tid][1] + redS[half][tid][2] + redS[half][tid][3];
        float q = redQ[half][tid][0] + redQ[half][tid][1] + redQ[half][tid][2] + redQ[half][tid][3];
        float mu = s * (1.f / 128.f);
        float var = q * (1.f / 128.f) - mu * mu;
        mu_s[half][tid] = mu;
        rs_s[half][tid] = rsqrtf(var + 1e-5f);
    }
    __syncthreads();
    float gg = ong[d], bb = onb[d];
    #pragma unroll
    for (int pos = 0; pos < 9; pos++)
        g_YN[p * 1152 + pos * 128 + d] =
            (yw[pos] - mu_s[half][pos]) * rs_s[half][pos] * gg + bb;
}

// ---------------- K5: addconv GEMM split-k=4 (R3 proven, grid (128,4)) ----------------
__global__ void __launch_bounds__(256) k_addconv() {
    __shared__ float As[32][33];
    __shared__ float Bs[32][68];
    const int tid = threadIdx.x;
    const int warp = tid >> 5, lane = tid & 31;
    const int p0 = blockIdx.x * 32;
    const int split = blockIdx.y;
    const int kb = split * 288;
    ull acc[4] = {0ull, 0ull, 0ull, 0ull};
    for (int kt = 0; kt < 288; kt += 32) {
        __syncthreads();
        for (int e = tid; e < 1024; e += 256) {
            int px = e >> 5, k = e & 31;
            As[px][k] = g_YN[(p0 + px) * 1152 + kb + kt + k];
        }
        for (int e = tid; e < 2048; e += 256) {
            int k = e >> 6, c = e & 63;
            Bs[k][c] = g_WT[(kb + kt + k) * 64 + c];
        }
        __syncthreads();
        #pragma unroll
        for (int k = 0; k < 32; k++) {
            float a = As[lane][k];
            ull ap = pack2(a, a);
            #pragma unroll
            for (int j = 0; j < 4; j++)
                acc[j] = fma2(ap, *(const ull*)&Bs[k][8 * warp + 2 * j], acc[j]);
        }
    }
    int p = p0 + lane;
    float r0, r1, r2, r3, r4, r5, r6, r7;
    unpack2(acc[0], r0, r1); unpack2(acc[1], r2, r3);
    unpack2(acc[2], r4, r5); unpack2(acc[3], r6, r7);
    float* dst = g_CORE + split * 262144 + p * 64 + 8 * warp;
    *(float4*)dst       = make_float4(r0, r1, r2, r3);
    *(float4*)(dst + 4) = make_float4(r4, r5, r6, r7);
}

// ---------------- K6: gate + out_proj + skip (16 px/block, R3 proven) ----------------
__global__ void __launch_bounds__(256) k_epilogue(
    const float* __restrict__ x, const float* __restrict__ acb,
    const float* __restrict__ skip_b, float* __restrict__ out) {
    __shared__ float ov[16][65], xv[16][65], zsm[16][65];
    __shared__ float wo[64][65], ws[64][65];
    const int tid = threadIdx.x;
    const int o = tid & 63, pg = tid >> 6;
    const int p0 = blockIdx.x * 16;

    for (int e = tid; e < 4096; e += 256) {
        int c = e >> 6, oo = e & 63;
        wo[c][oo] = g_WoT[e];
        ws[c][oo] = g_WsT[e];
    }
    #pragma unroll
    for (int i = 0; i < 4; i++) {
        int idx = tid + i * 256;
        int px2 = idx & 15, o2 = idx >> 4;
        zsm[px2][o2] = g_Zp[o2 * 4096 + p0 + px2];
    }
    __syncthreads();
    float acbv = __ldg(acb + o);
    #pragma unroll
    for (int i = 0; i < 4; i++) {
        int px = pg * 4 + i;
        int p = p0 + px;
        float core = g_CORE[p * 64 + o] + g_CORE[262144 + p * 64 + o]
                   + g_CORE[524288 + p * 64 + o] + g_CORE[786432 + p * 64 + o] + acbv;
        ov[px][o] = core * siluf(zsm[px][o]);
        xv[px][o] = x[p * 64 + o];
    }
    __syncthreads();
    float acc[4];
    float sb = __ldg(skip_b + o);
    #pragma unroll
    for (int i = 0; i < 4; i++) acc[i] = sb;
    #pragma unroll 4
    for (int c = 0; c < 64; c++) {
        float wov = wo[c][o], wsv = ws[c][o];
        #pragma unroll
        for (int i = 0; i < 4; i++) {
            int px = pg * 4 + i;
            acc[i] = fmaf(ov[px][c], wov, acc[i]);
            acc[i] = fmaf(xv[px][c], wsv, acc[i]);
        }
    }
    #pragma unroll
    for (int i = 0; i < 4; i++)
        out[(p0 + pg * 4 + i) * 64 + o] = acc[i];
}

// ---------------- launch ----------------
extern "C" void kernel_launch(void* const* d_in, const int* in_sizes, int n_in,
                              void* d_out, int out_size) {
    const float* x          = (const float*)d_in[0];
    const float* in_norm_g  = (const float*)d_in[1];
    const float* in_norm_b  = (const float*)d_in[2];
    const float* in_proj_w  = (const float*)d_in[3];
    const float* conv_w     = (const float*)d_in[4];
    const float* conv_b     = (const float*)d_in[5];
    const float* x_proj_w   = (const float*)d_in[6];
    const float* dt_w       = (const float*)d_in[7];
    const float* dt_b       = (const float*)d_in[8];
    const float* A_logs     = (const float*)d_in[9];
    const float* Ds         = (const float*)d_in[10];
    const float* out_norm_g = (const float*)d_in[11];
    const float* out_norm_b = (const float*)d_in[12];
    const float* addconv_w  = (const float*)d_in[13];
    const float* addconv_b  = (const float*)d_in[14];
    const float* skip_w     = (const float*)d_in[15];
    const float* skip_b     = (const float*)d_in[16];
    const float* out_proj_w = (const float*)d_in[17];
    float* out = (float*)d_out;

    k_pre<<<352, 256>>>(A_logs, addconv_w, out_proj_w, skip_w);
    k_ln<<<512, 256>>>(x, in_norm_g, in_norm_b);
    k_inproj<<<dim3(128, 6), 256>>>(in_proj_w);
    k_conv<<<512, 256>>>(conv_w, conv_b);
    k_xproj<<<dim3(64, 4), 288>>>(x_proj_w);
    k_scan<<<2048, 256>>>(dt_w, dt_b, Ds, out_norm_g, out_norm_b);
    k_addconv<<<dim3(128, 4), 256>>>();
    k_epilogue<<<256, 256>>>(x, addconv_b, skip_b, out);
}

// round 12
// speedup vs baseline: 1.2784x; 1.0098x over previous
#include <cuda_runtime.h>
#include <math.h>

#define LOG2E 1.4426950408889634f
typedef unsigned long long ull;

// ---------------- scratch (device globals; no allocation) ----------------
__device__ float g_XN  [4096 * 64];       // layernormed input [p][c]
__device__ float g_XI  [128 * 4096];      // in_proj xi, planar [d][hw]
__device__ float g_Zp  [64 * 4096];       // z gate, planar [o][p]
__device__ float g_XCT [4096 * 128];      // conv+silu output, pixel-major [p][d]
__device__ float g_PROJT[4096 * 144];     // x_proj output, pixel-major [p][144]
__device__ float g_YN  [4096 * 1152];     // post-LN window features [p][pos*128+d]
__device__ float g_CORE[4 * 4096 * 64];   // addconv partials (split-k=4) [s][p][o]
__device__ float g_ALc [512 * 16];        // -exp(A_logs) * log2e
__device__ float g_WT  [1152 * 64];       // addconv_w transposed [pos*128+d][o]
__device__ float g_WoT [64 * 64];         // out_proj_w^T [c][o]
__device__ float g_WsT [64 * 64];         // skip_w^T [c][o]
__device__ int   g_fastA = 1;             // A has geometric structure (sticky)

// ---------------- helpers ----------------
__device__ __forceinline__ float ex2f_fast(float x) {
    float y; asm("ex2.approx.f32 %0, %1;" : "=f"(y) : "f"(x)); return y;
}
__device__ __forceinline__ float softplusf(float x) {
    return x > 15.f ? x : __logf(1.f + __expf(x));
}
__device__ __forceinline__ float siluf(float x) {
    return x / (1.f + __expf(-x));
}
__device__ __forceinline__ int refl(int v) {
    return v < 0 ? -v : (v > 63 ? 126 - v : v);
}
__device__ __forceinline__ ull pack2(float a, float b) {
    ull r; asm("mov.b64 %0, {%1,%2};" : "=l"(r) : "f"(a), "f"(b)); return r;
}
__device__ __forceinline__ void unpack2(ull v, float& a, float& b) {
    asm("mov.b64 {%0,%1}, %2;" : "=f"(a), "=f"(b) : "l"(v));
}
__device__ __forceinline__ ull fma2(ull a, ull b, ull c) {
    ull d; asm("fma.rn.f32x2 %0, %1, %2, %3;" : "=l"(d) : "l"(a), "l"(b), "l"(c)); return d;
}
__device__ __forceinline__ ull mul2(ull a, ull b) {
    ull d; asm("mul.rn.f32x2 %0, %1, %2;" : "=l"(d) : "l"(a), "l"(b)); return d;
}

// ---------------- K0: precompute ----------------
__global__ void k_pre(const float* __restrict__ A_logs,
                      const float* __restrict__ addconv_w,
                      const float* __restrict__ out_proj_w,
                      const float* __restrict__ skip_w) {
    int idx = blockIdx.x * 256 + threadIdx.x;
    if (idx < 73728) {
        int o = idx & 63; int rest = idx >> 6;
        int d = rest & 127; int pos = rest >> 7;
        g_WT[idx] = addconv_w[o * 1152 + d * 9 + pos];
    } else if (idx < 73728 + 8192) {
        int j = idx - 73728;
        float e = expf(A_logs[j]);
        g_ALc[j] = -e * LOG2E;
        int n = j & 15;
        float e0 = expf(A_logs[j & ~15]);
        if (fabsf(e - (float)(n + 1) * e0) > 1e-4f * fmaxf(e, 1e-6f))
            atomicAnd(&g_fastA, 0);
    } else if (idx < 73728 + 8192 + 4096) {
        int j = idx - 73728 - 8192;
        int o = j & 63, c = j >> 6;
        g_WoT[j] = out_proj_w[o * 64 + c];
    } else if (idx < 73728 + 8192 + 8192) {
        int j = idx - 73728 - 8192 - 4096;
        int o = j & 63, c = j >> 6;
        g_WsT[j] = skip_w[o * 64 + c];
    }
}

// ---------------- K1a: layernorm ----------------
__global__ void __launch_bounds__(256) k_ln(
    const float* __restrict__ x, const float* __restrict__ g,
    const float* __restrict__ b) {
    int warp = threadIdx.x >> 5, lane = threadIdx.x & 31;
    int p = blockIdx.x * 8 + warp;
    float x0 = x[p * 64 + lane], x1 = x[p * 64 + lane + 32];
    float s = x0 + x1;
    #pragma unroll
    for (int off = 16; off > 0; off >>= 1) s += __shfl_xor_sync(0xffffffffu, s, off);
    float mu = s * (1.f / 64.f);
    float d0 = x0 - mu, d1 = x1 - mu;
    float q = d0 * d0 + d1 * d1;
    #pragma unroll
    for (int off = 16; off > 0; off >>= 1) q += __shfl_xor_sync(0xffffffffu, q, off);
    float rstd = rsqrtf(q * (1.f / 64.f) + 1e-5f);
    g_XN[p * 64 + lane]      = d0 * rstd * g[lane]      + b[lane];
    g_XN[p * 64 + lane + 32] = d1 * rstd * g[lane + 32] + b[lane + 32];
}

// ---------------- K1b: in_proj GEMM; grid (128, 6) ----------------
__global__ void __launch_bounds__(256) k_inproj(const float* __restrict__ ipw) {
    __shared__ float xs[32][65];
    __shared__ float ws[64][34];
    const int tid = threadIdx.x;
    const int warp = tid >> 5, lane = tid & 31;
    const int p0 = blockIdx.x * 32;
    const int cg = blockIdx.y * 32;
    for (int e = tid; e < 2048; e += 256) {
        int px = e >> 6, k = e & 63;
        xs[px][k] = g_XN[(p0 + px) * 64 + k];
    }
    for (int e = tid; e < 2048; e += 256) {
        int cc = e >> 6, k = e & 63;
        ws[k][cc] = ipw[(cg + cc) * 64 + k];
    }
    __syncthreads();
    ull a0 = 0ull, a1 = 0ull;
    #pragma unroll
    for (int k = 0; k < 64; k++) {
        float xv = xs[lane][k];
        ull xp = pack2(xv, xv);
        a0 = fma2(xp, *(const ull*)&ws[k][4 * warp],     a0);
        a1 = fma2(xp, *(const ull*)&ws[k][4 * warp + 2], a1);
    }
    int p = p0 + lane;
    float r0, r1, r2, r3;
    unpack2(a0, r0, r1); unpack2(a1, r2, r3);
    int c = cg + 4 * warp;
    float rv[4] = {r0, r1, r2, r3};
    #pragma unroll
    for (int j = 0; j < 4; j++) {
        int cj = c + j;
        if (cj < 128) g_XI[cj * 4096 + p] = rv[j];
        else          g_Zp[(cj - 128) * 4096 + p] = rv[j];
    }
}

// ---------------- K2: depthwise 3x3 conv (zero pad) + bias + silu ----------------
__global__ void __launch_bounds__(256) k_conv(
    const float* __restrict__ cw, const float* __restrict__ cb) {
    const int h  = blockIdx.x >> 3, dg = blockIdx.x & 7;
    const int tid = threadIdx.x;
    const int w = tid & 63, q = tid >> 6;
    const int d0 = dg * 16 + q * 4;
    float o[4];
    #pragma unroll
    for (int i = 0; i < 4; i++) {
        int d = d0 + i;
        float acc = __ldg(cb + d);
        #pragma unroll
        for (int ki = 0; ki < 3; ki++) {
            int hh = h + ki - 1;
            if (hh < 0 || hh > 63) continue;
            const float* row = g_XI + d * 4096 + hh * 64 + w;
            if (w > 0)  acc = fmaf(__ldg(cw + d * 9 + ki * 3 + 0), row[-1], acc);
                        acc = fmaf(__ldg(cw + d * 9 + ki * 3 + 1), row[0],  acc);
            if (w < 63) acc = fmaf(__ldg(cw + d * 9 + ki * 3 + 2), row[1],  acc);
        }
        o[i] = siluf(acc);
    }
    *(float4*)(g_XCT + (h * 64 + w) * 128 + d0) = make_float4(o[0], o[1], o[2], o[3]);
}

// ---------------- K3: x_proj GEMM v3: grid (64,4), 288 thr ----------------
__global__ void __launch_bounds__(288) k_xproj(const float* __restrict__ xpw) {
    __shared__ __align__(16) float xcT[64][66];   // [k-local][px]
    __shared__ ull wsd[64][36];                   // duplicated weight pairs
    const int tid = threadIdx.x;
    const int pxg = tid & 15;        // 16 groups of 4 px
    const int cq  = tid >> 4;        // 18 groups of 2 c
    const int p0 = blockIdx.x * 64;
    const int cg = blockIdx.y * 36;

    ull acc00 = 0ull, acc01 = 0ull, acc10 = 0ull, acc11 = 0ull;

    for (int kb = 0; kb < 128; kb += 64) {
        __syncthreads();
        for (int e = tid; e < 4096; e += 288) {
            int k = e & 63, px = e >> 6;
            xcT[k][px] = g_XCT[(p0 + px) * 128 + kb + k];
        }
        for (int e = tid; e < 2304; e += 288) {
            int k = e & 63, c = e >> 6;
            float wv = xpw[(cg + c) * 128 + kb + k];
            wsd[k][c] = pack2(wv, wv);
        }
        __syncthreads();
        #pragma unroll 4
        for (int k = 0; k < 64; k++) {
            ull xp0 = *(const ull*)&xcT[k][pxg * 4];
            ull xp1 = *(const ull*)&xcT[k][pxg * 4 + 2];
            ull w0 = wsd[k][cq * 2];
            ull w1 = wsd[k][cq * 2 + 1];
            acc00 = fma2(xp0, w0, acc00);
            acc01 = fma2(xp0, w1, acc01);
            acc10 = fma2(xp1, w0, acc10);
            acc11 = fma2(xp1, w1, acc11);
        }
    }
    float v[2][4];
    unpack2(acc00, v[0][0], v[0][1]);
    unpack2(acc10, v[0][2], v[0][3]);
    unpack2(acc01, v[1][0], v[1][1]);
    unpack2(acc11, v[1][2], v[1][3]);
    #pragma unroll
    for (int j = 0; j < 2; j++)
        #pragma unroll
        for (int i = 0; i < 4; i++)
            g_PROJT[(p0 + pxg * 4 + i) * 144 + cg + cq * 2 + j] = v[j][i];
}

// ---------------- K4: selective scan + combine + per-position LN ----------------
// This round: B/C smem reads vectorized to LDS.128; y split into 2 accumulators
__global__ void __launch_bounds__(256) k_scan(
    const float* __restrict__ dtw, const float* __restrict__ dtb,
    const float* __restrict__ Dsp, const float* __restrict__ ong,
    const float* __restrict__ onb) {
    const int half = threadIdx.x >> 7;
    const int tid  = threadIdx.x & 127;
    const int p = blockIdx.x * 2 + half;
    const int h = p >> 6, w = p & 63;
    const int d = tid;
    __shared__ __align__(16) float win[2][9][144];
    __shared__ float redS[2][9][4], redQ[2][9][4];
    __shared__ float mu_s[2][9], rs_s[2][9];

    const int fastA = g_fastA;

    for (int e = tid; e < 9 * 36; e += 128) {
        int pos = e / 36, c4 = e - pos * 36;
        int i = pos / 3, j = pos - 3 * (pos / 3);
        int hh = refl(h - 1 + i), ww = refl(w - 1 + j);
        ((float4*)win[half][pos])[c4] =
            ((const float4*)(g_PROJT + (hh * 64 + ww) * 144))[c4];
    }
    float u9[9];
    #pragma unroll
    for (int pos = 0; pos < 9; pos++) {
        int i = pos / 3, j = pos % 3;
        int hh = refl(h - 1 + i), ww = refl(w - 1 + j);
        u9[pos] = g_XCT[(hh * 64 + ww) * 128 + d];
    }
    __syncthreads();

    constexpr int POS[4][9] = {
        {0,1,2,3,4,5,6,7,8},
        {0,3,6,1,4,7,2,5,8},
        {8,7,6,5,4,3,2,1,0},
        {8,5,2,7,4,1,6,3,0}};
    constexpr int PKB[4] = {0, 72, 36, 108};

    float yw[9];
    #pragma unroll
    for (int t = 0; t < 9; t++) yw[t] = 0.f;

    #pragma unroll
    for (int k = 0; k < 4; k++) {
        int kd = k * 128 + d;
        float4 dw = __ldg((const float4*)(dtw + kd * 4));
        float db = __ldg(dtb + kd);
        float Dv = __ldg(Dsp + kd);
        float AL0 = g_ALc[kd * 16];
        float delta[9];
        #pragma unroll
        for (int l = 0; l < 9; l++) {
            float4 xr = *(const float4*)&win[half][POS[k][l]][PKB[k]];
            float s = db;
            s = fmaf(dw.x, xr.x, s); s = fmaf(dw.y, xr.y, s);
            s = fmaf(dw.z, xr.z, s); s = fmaf(dw.w, xr.w, s);
            delta[l] = softplusf(s);
        }
        ull hp[8];
        #pragma unroll
        for (int j = 0; j < 8; j++) hp[j] = 0ull;
        #pragma unroll
        for (int l = 0; l < 9; l++) {
            const int pos = POS[k][l];
            float dl = delta[l];
            float du = dl * u9[pos];
            ull dup = pack2(du, du);
            const longlong2* Bq = (const longlong2*)&win[half][pos][PKB[k] + 4];
            const longlong2* Cq = (const longlong2*)&win[half][pos][PKB[k] + 20];
            ull yp0 = 0ull, yp1 = 0ull;
            if (fastA) {
                float r  = ex2f_fast(dl * AL0);
                float r2 = r * r;
                ull rr  = pack2(r2, r2);
                ull dAp = pack2(r, r2);
                #pragma unroll
                for (int q = 0; q < 4; q++) {
                    longlong2 tb = Bq[q];
                    longlong2 tc = Cq[q];
                    if (q) dAp = mul2(dAp, rr);
                    hp[2*q]   = fma2(hp[2*q],   dAp, mul2(dup, (ull)tb.x));
                    yp0 = fma2(hp[2*q],   (ull)tc.x, yp0);
                    dAp = mul2(dAp, rr);
                    hp[2*q+1] = fma2(hp[2*q+1], dAp, mul2(dup, (ull)tb.y));
                    yp1 = fma2(hp[2*q+1], (ull)tc.y, yp1);
                }
            } else {
                #pragma unroll
                for (int q = 0; q < 4; q++) {
                    longlong2 tb = Bq[q];
                    longlong2 tc = Cq[q];
                    float4 al = *(const float4*)(g_ALc + kd * 16 + 4 * q);
                    ull dA0 = pack2(ex2f_fast(dl * al.x), ex2f_fast(dl * al.y));
                    ull dA1 = pack2(ex2f_fast(dl * al.z), ex2f_fast(dl * al.w));
                    hp[2*q]   = fma2(hp[2*q],   dA0, mul2(dup, (ull)tb.x));
                    yp0 = fma2(hp[2*q],   (ull)tc.x, yp0);
                    hp[2*q+1] = fma2(hp[2*q+1], dA1, mul2(dup, (ull)tb.y));
                    yp1 = fma2(hp[2*q+1], (ull)tc.y, yp1);
                }
            }
            float ya, yb, yc, yd2;
            unpack2(yp0, ya, yb);
            unpack2(yp1, yc, yd2);
            yw[pos] += fmaf(Dv, u9[pos], (ya + yb) + (yc + yd2));
        }
    }

    int warp = tid >> 5, lane = tid & 31;
    #pragma unroll
    for (int pos = 0; pos < 9; pos++) {
        float v = yw[pos], q = v * v;
        #pragma unroll
        for (int off = 16; off > 0; off >>= 1) {
            v += __shfl_xor_sync(0xffffffffu, v, off);
            q += __shfl_xor_sync(0xffffffffu, q, off);
        }
        if (lane == 0) { redS[half][pos][warp] = v; redQ[half][pos][warp] = q; }
    }
    __syncthreads();
    if (tid < 9) {
        float s = redS[half][tid][0] + redS[half][tid][1] + redS[half][tid][2] + redS[half][tid][3];
        float q = redQ[half][tid][0] + redQ[half][tid][1] + redQ[half][tid][2] + redQ[half][tid][3];
        float mu = s * (1.f / 128.f);
        float var = q * (1.f / 128.f) - mu * mu;
        mu_s[half][tid] = mu;
        rs_s[half][tid] = rsqrtf(var + 1e-5f);
    }
    __syncthreads();
    float gg = ong[d], bb = onb[d];
    #pragma unroll
    for (int pos = 0; pos < 9; pos++)
        g_YN[p * 1152 + pos * 128 + d] =
            (yw[pos] - mu_s[half][pos]) * rs_s[half][pos] * gg + bb;
}

// ---------------- K5: addconv GEMM split-k=4; B loads vectorized ----------------
__global__ void __launch_bounds__(256) k_addconv() {
    __shared__ float As[32][33];
    __shared__ __align__(16) float Bs[32][68];
    const int tid = threadIdx.x;
    const int warp = tid >> 5, lane = tid & 31;
    const int p0 = blockIdx.x * 32;
    const int split = blockIdx.y;
    const int kb = split * 288;
    ull acc[4] = {0ull, 0ull, 0ull, 0ull};
    for (int kt = 0; kt < 288; kt += 32) {
        __syncthreads();
        for (int e = tid; e < 1024; e += 256) {
            int px = e >> 5, k = e & 31;
            As[px][k] = g_YN[(p0 + px) * 1152 + kb + kt + k];
        }
        for (int e = tid; e < 2048; e += 256) {
            int k = e >> 6, c = e & 63;
            Bs[k][c] = g_WT[(kb + kt + k) * 64 + c];
        }
        __syncthreads();
        #pragma unroll
        for (int k = 0; k < 32; k++) {
            float a = As[lane][k];
            ull ap = pack2(a, a);
            const longlong2* Bq = (const longlong2*)&Bs[k][8 * warp];
            longlong2 b0 = Bq[0], b1 = Bq[1];
            acc[0] = fma2(ap, (ull)b0.x, acc[0]);
            acc[1] = fma2(ap, (ull)b0.y, acc[1]);
            acc[2] = fma2(ap, (ull)b1.x, acc[2]);
            acc[3] = fma2(ap, (ull)b1.y, acc[3]);
        }
    }
    int p = p0 + lane;
    float r0, r1, r2, r3, r4, r5, r6, r7;
    unpack2(acc[0], r0, r1); unpack2(acc[1], r2, r3);
    unpack2(acc[2], r4, r5); unpack2(acc[3], r6, r7);
    float* dst = g_CORE + split * 262144 + p * 64 + 8 * warp;
    *(float4*)dst       = make_float4(r0, r1, r2, r3);
    *(float4*)(dst + 4) = make_float4(r4, r5, r6, r7);
}

// ---------------- K6: gate + out_proj + skip (16 px/block) ----------------
__global__ void __launch_bounds__(256) k_epilogue(
    const float* __restrict__ x, const float* __restrict__ acb,
    const float* __restrict__ skip_b, float* __restrict__ out) {
    __shared__ float ov[16][65], xv[16][65], zsm[16][65];
    __shared__ float wo[64][65], ws[64][65];
    const int tid = threadIdx.x;
    const int o = tid & 63, pg = tid >> 6;
    const int p0 = blockIdx.x * 16;

    for (int e = tid; e < 4096; e += 256) {
        int c = e >> 6, oo = e & 63;
        wo[c][oo] = g_WoT[e];
        ws[c][oo] = g_WsT[e];
    }
    #pragma unroll
    for (int i = 0; i < 4; i++) {
        int idx = tid + i * 256;
        int px2 = idx & 15, o2 = idx >> 4;
        zsm[px2][o2] = g_Zp[o2 * 4096 + p0 + px2];
    }
    __syncthreads();
    float acbv = __ldg(acb + o);
    #pragma unroll
    for (int i = 0; i < 4; i++) {
        int px = pg * 4 + i;
        int p = p0 + px;
        float core = g_CORE[p * 64 + o] + g_CORE[262144 + p * 64 + o]
                   + g_CORE[524288 + p * 64 + o] + g_CORE[786432 + p * 64 + o] + acbv;
        ov[px][o] = core * siluf(zsm[px][o]);
        xv[px][o] = x[p * 64 + o];
    }
    __syncthreads();
    float acc[4];
    float sb = __ldg(skip_b + o);
    #pragma unroll
    for (int i = 0; i < 4; i++) acc[i] = sb;
    #pragma unroll 4
    for (int c = 0; c < 64; c++) {
        float wov = wo[c][o], wsv = ws[c][o];
        #pragma unroll
        for (int i = 0; i < 4; i++) {
            int px = pg * 4 + i;
            acc[i] = fmaf(ov[px][c], wov, acc[i]);
            acc[i] = fmaf(xv[px][c], wsv, acc[i]);
        }
    }
    #pragma unroll
    for (int i = 0; i < 4; i++)
        out[(p0 + pg * 4 + i) * 64 + o] = acc[i];
}

// ---------------- launch ----------------
extern "C" void kernel_launch(void* const* d_in, const int* in_sizes, int n_in,
                              void* d_out, int out_size) {
    const float* x          = (const float*)d_in[0];
    const float* in_norm_g  = (const float*)d_in[1];
    const float* in_norm_b  = (const float*)d_in[2];
    const float* in_proj_w  = (const float*)d_in[3];
    const float* conv_w     = (const float*)d_in[4];
    const float* conv_b     = (const float*)d_in[5];
    const float* x_proj_w   = (const float*)d_in[6];
    const float* dt_w       = (const float*)d_in[7];
    const float* dt_b       = (const float*)d_in[8];
    const float* A_logs     = (const float*)d_in[9];
    const float* Ds         = (const float*)d_in[10];
    const float* out_norm_g = (const float*)d_in[11];
    const float* out_norm_b = (const float*)d_in[12];
    const float* addconv_w  = (const float*)d_in[13];
    const float* addconv_b  = (const float*)d_in[14];
    const float* skip_w     = (const float*)d_in[15];
    const float* skip_b     = (const float*)d_in[16];
    const float* out_proj_w = (const float*)d_in[17];
    float* out = (float*)d_out;

    k_pre<<<352, 256>>>(A_logs, addconv_w, out_proj_w, skip_w);
    k_ln<<<512, 256>>>(x, in_norm_g, in_norm_b);
    k_inproj<<<dim3(128, 6), 256>>>(in_proj_w);
    k_conv<<<512, 256>>>(conv_w, conv_b);
    k_xproj<<<dim3(64, 4), 288>>>(x_proj_w);
    k_scan<<<2048, 256>>>(dt_w, dt_b, Ds, out_norm_g, out_norm_b);
    k_addconv<<<dim3(128, 4), 256>>>();
    k_epilogue<<<256, 256>>>(x, addconv_b, skip_b, out);
}